// round 1
// baseline (speedup 1.0000x reference)
#include <cuda_runtime.h>
#include <cstdint>
#include <math.h>

#define HIDDEN 2048
#define NHEADS 32
#define NKV    8
#define HD     64
#define KV_REP 4
#define INTER  8192
#define BATCH  2
#define QLEN   2048
#define KLEN   2048
#define MTOT   (BATCH*QLEN)

// ---------------- scratch (device globals: no allocation allowed) ----------------
__device__ float g_normed [MTOT*HIDDEN];
__device__ float g_q      [MTOT*HIDDEN];
__device__ float g_vt     [BATCH*NKV*HD*KLEN];
__device__ float g_scores [(size_t)BATCH*NHEADS*QLEN*KLEN];  // 1.07 GB
__device__ float g_attn   [MTOT*HIDDEN];
__device__ float g_hidden [MTOT*HIDDEN];
__device__ float g_normed2[MTOT*HIDDEN];
__device__ float g_gate   [(size_t)MTOT*INTER];
__device__ float g_up     [(size_t)MTOT*INTER];

// ---------------- helpers ----------------
__device__ __forceinline__ uint32_t f2tf(float x){
    uint32_t r; asm("cvt.rna.tf32.f32 %0, %1;" : "=r"(r) : "f"(x)); return r;
}
__device__ __forceinline__ void mma8(float* c, const uint32_t* a, const uint32_t* b){
    asm volatile("mma.sync.aligned.m16n8k8.row.col.f32.tf32.tf32.f32 "
        "{%0,%1,%2,%3}, {%4,%5,%6,%7}, {%8,%9}, {%0,%1,%2,%3};"
        : "+f"(c[0]), "+f"(c[1]), "+f"(c[2]), "+f"(c[3])
        : "r"(a[0]), "r"(a[1]), "r"(a[2]), "r"(a[3]), "r"(b[0]), "r"(b[1]));
}

__device__ __forceinline__ float blockSum(float v){
    __shared__ float sh[8];
    __shared__ float res;
    int lane = threadIdx.x & 31, w = threadIdx.x >> 5;
    #pragma unroll
    for (int o=16;o;o>>=1) v += __shfl_xor_sync(0xffffffffu, v, o);
    if (lane==0) sh[w] = v;
    __syncthreads();
    if (w==0){
        float x = (lane < 8) ? sh[lane] : 0.f;
        #pragma unroll
        for (int o=4;o;o>>=1) x += __shfl_xor_sync(0xffffffffu, x, o);
        if (lane==0) res = x;
    }
    __syncthreads();
    return res;
}
__device__ __forceinline__ float blockMax(float v){
    __shared__ float sh[8];
    __shared__ float res;
    int lane = threadIdx.x & 31, w = threadIdx.x >> 5;
    #pragma unroll
    for (int o=16;o;o>>=1) v = fmaxf(v, __shfl_xor_sync(0xffffffffu, v, o));
    if (lane==0) sh[w] = v;
    __syncthreads();
    if (w==0){
        float x = (lane < 8) ? sh[lane] : -1e30f;
        #pragma unroll
        for (int o=4;o;o>>=1) x = fmaxf(x, __shfl_xor_sync(0xffffffffu, x, o));
        if (lane==0) res = x;
    }
    __syncthreads();
    return res;
}

// ---------------- tf32 GEMM: C[M,N] = A[M,K] * B[N,K]^T (+Res) ----------------
// Batched over grid.z: z -> (bb = z/nh, hh = z%nh); per-matrix offsets via strides.
#define BM 128
#define BN 128
#define BK 16

__global__ __launch_bounds__(256)
void gemm_tf32(const float* __restrict__ Ag, const float* __restrict__ Bg,
               float* __restrict__ Cg, const float* __restrict__ Resg,
               int M, int N, int K, int lda, int ldb, int ldc,
               long long aSb, long long aSh, long long bSb, long long bSh, int bHdiv,
               long long cSb, long long cSh, int nh)
{
    const int bb = blockIdx.z / nh, hh = blockIdx.z % nh;
    const float* A  = Ag + bb*aSb + (long long)hh*aSh;
    const float* Bp = Bg + bb*bSb + (long long)(hh/bHdiv)*bSh;
    const long long coff = bb*cSb + (long long)hh*cSh;
    float* C = Cg + coff;
    const float* Res = Resg ? (Resg + coff) : (const float*)0;

    __shared__ uint32_t As[2][BK][BM+4];
    __shared__ uint32_t Bs[2][BK][BN+4];

    const int tid  = threadIdx.x;
    const int lane = tid & 31, warp = tid >> 5;
    const int wm = (warp & 1)*64, wn = (warp >> 1)*32;
    const int g = lane >> 2, tg = lane & 3;
    const int m0 = blockIdx.y * BM, n0 = blockIdx.x * BN;

    float acc[4][4][4];
    #pragma unroll
    for (int i=0;i<4;i++)
        #pragma unroll
        for (int j=0;j<4;j++)
            #pragma unroll
            for (int t=0;t<4;t++) acc[i][j][t]=0.f;

    // each thread stages 2 float4 of A and 2 of B per k-block
    int rowT[2], c4T[2];
    #pragma unroll
    for (int i=0;i<2;i++){ int idx = tid + i*256; rowT[i] = idx >> 2; c4T[i] = idx & 3; }
    float4 stA[2], stB[2];

    const int nkb = K / BK;

    // prologue: load k-block 0
    #pragma unroll
    for (int i=0;i<2;i++){
        int gm = m0 + rowT[i];
        int gk = c4T[i]*4;
        stA[i] = (gm < M) ? *(const float4*)(A  + (long long)gm*lda + gk) : make_float4(0,0,0,0);
        int gn = n0 + rowT[i];
        stB[i] = (gn < N) ? *(const float4*)(Bp + (long long)gn*ldb + gk) : make_float4(0,0,0,0);
    }
    #pragma unroll
    for (int i=0;i<2;i++){
        As[0][c4T[i]*4+0][rowT[i]] = f2tf(stA[i].x);
        As[0][c4T[i]*4+1][rowT[i]] = f2tf(stA[i].y);
        As[0][c4T[i]*4+2][rowT[i]] = f2tf(stA[i].z);
        As[0][c4T[i]*4+3][rowT[i]] = f2tf(stA[i].w);
        Bs[0][c4T[i]*4+0][rowT[i]] = f2tf(stB[i].x);
        Bs[0][c4T[i]*4+1][rowT[i]] = f2tf(stB[i].y);
        Bs[0][c4T[i]*4+2][rowT[i]] = f2tf(stB[i].z);
        Bs[0][c4T[i]*4+3][rowT[i]] = f2tf(stB[i].w);
    }
    __syncthreads();

    for (int kb=0; kb<nkb; kb++){
        const int buf = kb & 1;
        if (kb+1 < nkb){
            int gk = (kb+1)*BK;
            #pragma unroll
            for (int i=0;i<2;i++){
                int gm = m0 + rowT[i];
                stA[i] = (gm < M) ? *(const float4*)(A  + (long long)gm*lda + gk + c4T[i]*4) : make_float4(0,0,0,0);
                int gn = n0 + rowT[i];
                stB[i] = (gn < N) ? *(const float4*)(Bp + (long long)gn*ldb + gk + c4T[i]*4) : make_float4(0,0,0,0);
            }
        }
        #pragma unroll
        for (int ks=0; ks<BK; ks+=8){
            uint32_t af[4][4], bf[4][2];
            #pragma unroll
            for (int mi=0;mi<4;mi++){
                int mm = wm + mi*16 + g;
                af[mi][0] = As[buf][ks+tg  ][mm];
                af[mi][1] = As[buf][ks+tg  ][mm+8];
                af[mi][2] = As[buf][ks+tg+4][mm];
                af[mi][3] = As[buf][ks+tg+4][mm+8];
            }
            #pragma unroll
            for (int ni=0;ni<4;ni++){
                int nn = wn + ni*8 + g;
                bf[ni][0] = Bs[buf][ks+tg  ][nn];
                bf[ni][1] = Bs[buf][ks+tg+4][nn];
            }
            #pragma unroll
            for (int mi=0;mi<4;mi++)
                #pragma unroll
                for (int ni=0;ni<4;ni++)
                    mma8(acc[mi][ni], af[mi], bf[ni]);
        }
        if (kb+1 < nkb){
            const int nb = 1-buf;
            #pragma unroll
            for (int i=0;i<2;i++){
                As[nb][c4T[i]*4+0][rowT[i]] = f2tf(stA[i].x);
                As[nb][c4T[i]*4+1][rowT[i]] = f2tf(stA[i].y);
                As[nb][c4T[i]*4+2][rowT[i]] = f2tf(stA[i].z);
                As[nb][c4T[i]*4+3][rowT[i]] = f2tf(stA[i].w);
                Bs[nb][c4T[i]*4+0][rowT[i]] = f2tf(stB[i].x);
                Bs[nb][c4T[i]*4+1][rowT[i]] = f2tf(stB[i].y);
                Bs[nb][c4T[i]*4+2][rowT[i]] = f2tf(stB[i].z);
                Bs[nb][c4T[i]*4+3][rowT[i]] = f2tf(stB[i].w);
            }
        }
        __syncthreads();
    }

    // epilogue
    #pragma unroll
    for (int mi=0;mi<4;mi++){
        #pragma unroll
        for (int ni=0;ni<4;ni++){
            int r0 = m0 + wm + mi*16 + g;
            int r1 = r0 + 8;
            int c0 = n0 + wn + ni*8 + tg*2;
            const float* cc = acc[mi][ni];
            if (c0 < N){
                if (r0 < M){
                    long long o0 = (long long)r0*ldc + c0;
                    float v0 = cc[0], v1 = cc[1];
                    if (Res){ v0 += Res[o0]; v1 += Res[o0+1]; }
                    C[o0] = v0; C[o0+1] = v1;
                }
                if (r1 < M){
                    long long o1 = (long long)r1*ldc + c0;
                    float v2 = cc[2], v3 = cc[3];
                    if (Res){ v2 += Res[o1]; v3 += Res[o1+1]; }
                    C[o1] = v2; C[o1+1] = v3;
                }
            }
        }
    }
}

// ---------------- RMSNorm ----------------
__global__ void rmsnorm_k(const float* __restrict__ x, const float* __restrict__ w,
                          float* __restrict__ o)
{
    size_t row = blockIdx.x;
    const float* xr = x + row*HIDDEN;
    float* orow = o + row*HIDDEN;
    float s = 0.f;
    for (int i=threadIdx.x; i<HIDDEN; i+=256){ float v = xr[i]; s += v*v; }
    s = blockSum(s);
    float rs = rsqrtf(s*(1.f/HIDDEN) + 1e-5f);
    for (int i=threadIdx.x; i<HIDDEN; i+=256) orow[i] = xr[i]*rs*w[i];
}

// ---------------- masked softmax over scores rows ----------------
__global__ void softmax_mask(float* __restrict__ S, const int* __restrict__ cuq,
                             const int* __restrict__ cuk)
{
    size_t row = blockIdx.x;                 // over BATCH*NHEADS*QLEN
    int q = (int)(row & (QLEN-1));
    float* s = S + row*(size_t)KLEN;
    int cq1 = cuq[1], cq2 = cuq[2];
    int ck1 = cuk[1], ck2 = cuk[2];
    int segq = (q>=cq1) + (q>=cq2);
    float vals[8];
    float mx = -1e30f;
    #pragma unroll
    for (int j=0;j<8;j++){
        int k = threadIdx.x + j*256;
        int segk = (k>=ck1) + (k>=ck2);
        float v = (segk==segq && k<=q) ? s[k]*0.125f : -1e30f;
        vals[j] = v;
        mx = fmaxf(mx, v);
    }
    mx = blockMax(mx);
    float sum = 0.f;
    #pragma unroll
    for (int j=0;j<8;j++){
        float e = expf(vals[j]-mx);
        vals[j] = e; sum += e;
    }
    sum = blockSum(sum);
    float inv = 1.f/sum;
    #pragma unroll
    for (int j=0;j<8;j++) s[threadIdx.x + j*256] = vals[j]*inv;
}

// ---------------- SiLU(gate)*up, in place into gate ----------------
__global__ void silumul_k(float* __restrict__ gbuf, const float* __restrict__ ubuf, int n)
{
    int i = blockIdx.x*256 + threadIdx.x;
    if (i < n){ float x = gbuf[i]; gbuf[i] = (x/(1.f+expf(-x))) * ubuf[i]; }
}

// ---------------- V transpose: [B,K,NKV,HD] -> [B,NKV,HD,K] ----------------
__global__ void vtrans_k(const float* __restrict__ v, float* __restrict__ vt)
{
    int idx = blockIdx.x*256 + threadIdx.x;          // total 2*2048*8*64 = 2^21
    if (idx >= BATCH*KLEN*NKV*HD) return;
    int d  = idx & 63;
    int kv = (idx>>6) & 7;
    int k  = (idx>>9) & 2047;
    int b  = idx>>20;
    vt[((((size_t)b*NKV+kv)*HD+d)<<11) + k] = v[idx];
}

// ---------------- launch ----------------
extern "C" void kernel_launch(void* const* d_in, const int* in_sizes, int n_in,
                              void* d_out, int out_size)
{
    const float* hs   = (const float*)d_in[0];
    const float* kst  = (const float*)d_in[1];
    const float* vst  = (const float*)d_in[2];
    const float* wln1 = (const float*)d_in[4];
    const float* wln2 = (const float*)d_in[5];
    const float* wq   = (const float*)d_in[6];
    const float* wo   = (const float*)d_in[7];
    const float* wg   = (const float*)d_in[8];
    const float* wu   = (const float*)d_in[9];
    const float* wd   = (const float*)d_in[10];
    const int*   cuq  = (const int*)d_in[11];
    const int*   cuk  = (const int*)d_in[12];
    float* out = (float*)d_out;

    float *nrm,*qb,*vt,*sc,*attn,*hid,*nrm2,*gate,*up;
    cudaGetSymbolAddress((void**)&nrm,  g_normed);
    cudaGetSymbolAddress((void**)&qb,   g_q);
    cudaGetSymbolAddress((void**)&vt,   g_vt);
    cudaGetSymbolAddress((void**)&sc,   g_scores);
    cudaGetSymbolAddress((void**)&attn, g_attn);
    cudaGetSymbolAddress((void**)&hid,  g_hidden);
    cudaGetSymbolAddress((void**)&nrm2, g_normed2);
    cudaGetSymbolAddress((void**)&gate, g_gate);
    cudaGetSymbolAddress((void**)&up,   g_up);

    dim3 blk(256);

    // 1. RMSNorm1
    rmsnorm_k<<<MTOT, 256>>>(hs, wln1, nrm);

    // 2. Q = normed @ wq^T   [4096,2048]
    gemm_tf32<<<dim3(HIDDEN/BN, MTOT/BM, 1), blk>>>(nrm, wq, qb, nullptr,
        MTOT, HIDDEN, HIDDEN, HIDDEN, HIDDEN, HIDDEN,
        0,0, 0,0, 1, 0,0, 1);

    // 3. V transpose
    vtrans_k<<<(BATCH*KLEN*NKV*HD+255)/256, 256>>>(vst, vt);

    // 4. scores[b,h] = Q_h K_h^T   batched z = b*32+h
    gemm_tf32<<<dim3(KLEN/BN, QLEN/BM, BATCH*NHEADS), blk>>>(qb, kst, sc, nullptr,
        QLEN, KLEN, HD, HIDDEN, NKV*HD, KLEN,
        (long long)QLEN*HIDDEN, HD,
        (long long)KLEN*NKV*HD, HD, KV_REP,
        (long long)NHEADS*QLEN*KLEN, (long long)QLEN*KLEN, NHEADS);

    // 5. masked softmax
    softmax_mask<<<BATCH*NHEADS*QLEN, 256>>>(sc, cuq, cuk);

    // 6. attn[b,:,h,:] = P V   batched
    gemm_tf32<<<dim3(1, QLEN/BM, BATCH*NHEADS), blk>>>(sc, vt, attn, nullptr,
        QLEN, HD, KLEN, KLEN, KLEN, HIDDEN,
        (long long)NHEADS*QLEN*KLEN, (long long)QLEN*KLEN,
        (long long)NKV*HD*KLEN, (long long)HD*KLEN, KV_REP,
        (long long)QLEN*HIDDEN, HD, NHEADS);

    // 7. hidden = residual + attn @ wo^T
    gemm_tf32<<<dim3(HIDDEN/BN, MTOT/BM, 1), blk>>>(attn, wo, hid, hs,
        MTOT, HIDDEN, HIDDEN, HIDDEN, HIDDEN, HIDDEN,
        0,0, 0,0, 1, 0,0, 1);

    // 8. RMSNorm2
    rmsnorm_k<<<MTOT, 256>>>(hid, wln2, nrm2);

    // 9/10. gate, up GEMMs [4096,8192]
    gemm_tf32<<<dim3(INTER/BN, MTOT/BM, 1), blk>>>(nrm2, wg, gate, nullptr,
        MTOT, INTER, HIDDEN, HIDDEN, HIDDEN, INTER,
        0,0, 0,0, 1, 0,0, 1);
    gemm_tf32<<<dim3(INTER/BN, MTOT/BM, 1), blk>>>(nrm2, wu, up, nullptr,
        MTOT, INTER, HIDDEN, HIDDEN, HIDDEN, INTER,
        0,0, 0,0, 1, 0,0, 1);

    // 11. silu(gate)*up
    silumul_k<<<(MTOT*INTER+255)/256, 256>>>(gate, up, MTOT*INTER);

    // 12. out = hidden + h @ wd^T
    gemm_tf32<<<dim3(HIDDEN/BN, MTOT/BM, 1), blk>>>(gate, wd, out, hid,
        MTOT, HIDDEN, INTER, INTER, INTER, HIDDEN,
        0,0, 0,0, 1, 0,0, 1);
}

// round 2
// speedup vs baseline: 2.9019x; 2.9019x over previous
#include <cuda_runtime.h>
#include <cuda_fp16.h>
#include <cstdint>
#include <math.h>

#define HIDDEN 2048
#define NHEADS 32
#define NKV    8
#define HD     64
#define INTER  8192
#define BATCH  2
#define QLEN   2048
#define KLEN   2048
#define MTOT   (BATCH*QLEN)

// ---------------- scratch ----------------
__device__ float g_normed [MTOT*HIDDEN];
__device__ float g_q      [MTOT*HIDDEN];
__device__ float g_attn   [MTOT*HIDDEN];
__device__ float g_hidden [MTOT*HIDDEN];
__device__ float g_normed2[MTOT*HIDDEN];
__device__ float g_gate   [(size_t)MTOT*INTER];

// ---------------- helpers ----------------
__device__ __forceinline__ uint32_t packh2(float a, float b){
    __half2 h = __floats2half2_rn(a, b);
    return *reinterpret_cast<uint32_t*>(&h);
}
__device__ __forceinline__ void mma16816(float* c, const uint32_t* a, uint32_t b0, uint32_t b1){
    asm volatile("mma.sync.aligned.m16n8k16.row.col.f32.f16.f16.f32 "
        "{%0,%1,%2,%3}, {%4,%5,%6,%7}, {%8,%9}, {%0,%1,%2,%3};"
        : "+f"(c[0]), "+f"(c[1]), "+f"(c[2]), "+f"(c[3])
        : "r"(a[0]), "r"(a[1]), "r"(a[2]), "r"(a[3]), "r"(b0), "r"(b1));
}
__device__ __forceinline__ float blockSum(float v){
    __shared__ float sh[8];
    __shared__ float res;
    int lane = threadIdx.x & 31, w = threadIdx.x >> 5;
    #pragma unroll
    for (int o=16;o;o>>=1) v += __shfl_xor_sync(0xffffffffu, v, o);
    if (lane==0) sh[w] = v;
    __syncthreads();
    if (w==0){
        float x = (lane < 8) ? sh[lane] : 0.f;
        #pragma unroll
        for (int o=4;o;o>>=1) x += __shfl_xor_sync(0xffffffffu, x, o);
        if (lane==0) res = x;
    }
    __syncthreads();
    return res;
}

// ---------------- fp16 GEMM: C[M,N] = A[M,K] * B[N,K]^T (+epilogue) ----------------
// mode 0: C = acc; mode 1: C = acc + Res; mode 2: C = silu(Res)*acc
__global__ __launch_bounds__(256,2)
void gemm_h(const float* __restrict__ A, const float* __restrict__ B,
            float* C, const float* Res, int M, int N, int K, int mode)
{
    __shared__ __half As[2][128][40];
    __shared__ __half Bs[2][128][40];

    const int tid  = threadIdx.x;
    const int lane = tid & 31, warp = tid >> 5;
    const int g = lane >> 2, tg = lane & 3;
    const int wm = (warp & 1)*64, wn = (warp >> 1)*32;
    const int m0 = blockIdx.y * 128, n0 = blockIdx.x * 128;

    const int sf4   = tid & 7;     // float4 index within a 32-col row
    const int srow0 = tid >> 3;    // 0..31, +32*i

    float acc[4][4][4];
    #pragma unroll
    for (int i=0;i<4;i++)
        #pragma unroll
        for (int j=0;j<4;j++){ acc[i][j][0]=0.f; acc[i][j][1]=0.f; acc[i][j][2]=0.f; acc[i][j][3]=0.f; }

    uint2 ha[4], hb[4];
    const int nkb = K / 32;

    // prologue: stage kb=0
    #pragma unroll
    for (int i=0;i<4;i++){
        int row = srow0 + i*32;
        float4 a4 = *(const float4*)(A + (size_t)(m0+row)*K + sf4*4);
        float4 b4 = *(const float4*)(B + (size_t)(n0+row)*K + sf4*4);
        ha[i] = make_uint2(packh2(a4.x,a4.y), packh2(a4.z,a4.w));
        hb[i] = make_uint2(packh2(b4.x,b4.y), packh2(b4.z,b4.w));
    }
    #pragma unroll
    for (int i=0;i<4;i++){
        int row = srow0 + i*32;
        *(uint2*)&As[0][row][sf4*4] = ha[i];
        *(uint2*)&Bs[0][row][sf4*4] = hb[i];
    }
    __syncthreads();

    for (int kb=0; kb<nkb; kb++){
        const int buf = kb & 1;
        if (kb+1 < nkb){
            const float* Ap = A + (size_t)m0*K + (kb+1)*32 + sf4*4;
            const float* Bp = B + (size_t)n0*K + (kb+1)*32 + sf4*4;
            #pragma unroll
            for (int i=0;i<4;i++){
                int row = srow0 + i*32;
                float4 a4 = *(const float4*)(Ap + (size_t)row*K);
                float4 b4 = *(const float4*)(Bp + (size_t)row*K);
                ha[i] = make_uint2(packh2(a4.x,a4.y), packh2(a4.z,a4.w));
                hb[i] = make_uint2(packh2(b4.x,b4.y), packh2(b4.z,b4.w));
            }
        }
        #pragma unroll
        for (int s=0;s<2;s++){
            const int c0 = s*16 + 2*tg;
            uint32_t af[4][4], bf[4][2];
            #pragma unroll
            for (int mi=0;mi<4;mi++){
                int m = wm + mi*16 + g;
                af[mi][0] = *(const uint32_t*)&As[buf][m  ][c0];
                af[mi][1] = *(const uint32_t*)&As[buf][m+8][c0];
                af[mi][2] = *(const uint32_t*)&As[buf][m  ][c0+8];
                af[mi][3] = *(const uint32_t*)&As[buf][m+8][c0+8];
            }
            #pragma unroll
            for (int ni=0;ni<4;ni++){
                int n = wn + ni*8 + g;
                bf[ni][0] = *(const uint32_t*)&Bs[buf][n][c0];
                bf[ni][1] = *(const uint32_t*)&Bs[buf][n][c0+8];
            }
            #pragma unroll
            for (int mi=0;mi<4;mi++)
                #pragma unroll
                for (int ni=0;ni<4;ni++)
                    mma16816(acc[mi][ni], af[mi], bf[ni][0], bf[ni][1]);
        }
        if (kb+1 < nkb){
            const int nb = buf ^ 1;
            #pragma unroll
            for (int i=0;i<4;i++){
                int row = srow0 + i*32;
                *(uint2*)&As[nb][row][sf4*4] = ha[i];
                *(uint2*)&Bs[nb][row][sf4*4] = hb[i];
            }
        }
        __syncthreads();
    }

    // epilogue
    #pragma unroll
    for (int mi=0;mi<4;mi++){
        #pragma unroll
        for (int ni=0;ni<4;ni++){
            int r0 = m0 + wm + mi*16 + g;
            int r1 = r0 + 8;
            int c  = n0 + wn + ni*8 + 2*tg;
            const float* a = acc[mi][ni];
            size_t o0 = (size_t)r0*N + c;
            size_t o1 = (size_t)r1*N + c;
            float v0=a[0], v1=a[1], v2=a[2], v3=a[3];
            if (mode == 1){
                v0 += Res[o0]; v1 += Res[o0+1];
                v2 += Res[o1]; v3 += Res[o1+1];
            } else if (mode == 2){
                float g0 = Res[o0], g1 = Res[o0+1], g2 = Res[o1], g3 = Res[o1+1];
                v0 *= g0/(1.f+__expf(-g0)); v1 *= g1/(1.f+__expf(-g1));
                v2 *= g2/(1.f+__expf(-g2)); v3 *= g3/(1.f+__expf(-g3));
            }
            float2 p0 = make_float2(v0,v1), p1 = make_float2(v2,v3);
            *(float2*)&C[o0] = p0;
            *(float2*)&C[o1] = p1;
        }
    }
}

// ---------------- RMSNorm ----------------
__global__ void rmsnorm_k(const float* __restrict__ x, const float* __restrict__ w,
                          float* __restrict__ o)
{
    size_t row = blockIdx.x;
    const float* xr = x + row*HIDDEN;
    float* orow = o + row*HIDDEN;
    float s = 0.f;
    for (int i=threadIdx.x; i<HIDDEN; i+=256){ float v = xr[i]; s += v*v; }
    s = blockSum(s);
    float rs = rsqrtf(s*(1.f/HIDDEN) + 1e-5f);
    for (int i=threadIdx.x; i<HIDDEN; i+=256) orow[i] = xr[i]*rs*w[i];
}

// ---------------- fused flash attention ----------------
// grid: (QLEN/128, BATCH*NHEADS). 8 warps, each owns 16 q rows.
__global__ __launch_bounds__(256,1)
void flash_attn(const float* __restrict__ q, const float* __restrict__ kst,
                const float* __restrict__ vst, float* __restrict__ o,
                const int* __restrict__ cuq, const int* __restrict__ cuk)
{
    __shared__ __half Ks[128][72];
    __shared__ __half Vts[64][136];

    const int tid  = threadIdx.x;
    const int lane = tid & 31, warp = tid >> 5;
    const int g = lane >> 2, tg = lane & 3;
    const int bh = blockIdx.y;
    const int b = bh >> 5, h = bh & 31, kv = h >> 2;
    const int q0 = blockIdx.x * 128;
    const int wq = warp * 16;

    const int cq1 = cuq[1], cq2 = cuq[2];
    const int ck1 = cuk[1], ck2 = cuk[2];

    // Q fragments straight from gmem (scaled by 1/sqrt(64))
    const int qg0 = q0 + wq + g, qg1 = qg0 + 8;
    const float* qr0 = q + ((size_t)(b*QLEN + qg0))*HIDDEN + h*HD;
    const float* qr1 = q + ((size_t)(b*QLEN + qg1))*HIDDEN + h*HD;
    uint32_t qf[4][4];
    #pragma unroll
    for (int s=0;s<4;s++){
        float2 x0 = *(const float2*)(qr0 + s*16 + 2*tg);
        float2 x1 = *(const float2*)(qr1 + s*16 + 2*tg);
        float2 x2 = *(const float2*)(qr0 + s*16 + 2*tg + 8);
        float2 x3 = *(const float2*)(qr1 + s*16 + 2*tg + 8);
        qf[s][0] = packh2(x0.x*0.125f, x0.y*0.125f);
        qf[s][1] = packh2(x1.x*0.125f, x1.y*0.125f);
        qf[s][2] = packh2(x2.x*0.125f, x2.y*0.125f);
        qf[s][3] = packh2(x3.x*0.125f, x3.y*0.125f);
    }

    const int sq0 = (qg0>=cq1)+(qg0>=cq2);
    const int sq1 = (qg1>=cq1)+(qg1>=cq2);
    // warp-uniform segment of warp's rows for fast-path check
    const int wlo = q0 + wq, whi = wlo + 15;
    const int sqa = (wlo>=cq1)+(wlo>=cq2);
    const int sqb = (whi>=cq1)+(whi>=cq2);

    float oacc[8][4];
    #pragma unroll
    for (int i=0;i<8;i++){ oacc[i][0]=0.f; oacc[i][1]=0.f; oacc[i][2]=0.f; oacc[i][3]=0.f; }
    float mr0 = -1e20f, mr1 = -1e20f, l0 = 0.f, l1 = 0.f;

    // tile range from CTA's q rows
    int segA = (q0>=cq1)+(q0>=cq2);
    int segB = (q0+127>=cq1)+(q0+127>=cq2);
    int klo, khi;
    if (segA == segB){
        int klos = (segA==0) ? 0 : ((segA==1) ? ck1 : ck2);
        int khis = (segA==0) ? ck1 : ((segA==1) ? ck2 : KLEN);
        klo = klos;
        khi = min(khis, q0+128);
    } else { klo = 0; khi = q0+128; }
    const int t0 = klo >> 7, t1 = (khi + 127) >> 7;

    const int lrow = tid >> 4;          // 0..15 (+16*i)
    const int lf4  = tid & 15;          // float4 col within 64

    for (int t=t0; t<t1; t++){
        const int k0 = t << 7;
        __syncthreads();
        // load K,V tiles (128 x 64)
        #pragma unroll
        for (int i=0;i<8;i++){
            int row = lrow + i*16;
            size_t base = (((size_t)(b*KLEN + k0 + row))*NKV + kv)*HD + lf4*4;
            float4 k4 = *(const float4*)(kst + base);
            float4 v4 = *(const float4*)(vst + base);
            *(uint2*)&Ks[row][lf4*4] = make_uint2(packh2(k4.x,k4.y), packh2(k4.z,k4.w));
            Vts[lf4*4+0][row] = __float2half(v4.x);
            Vts[lf4*4+1][row] = __float2half(v4.y);
            Vts[lf4*4+2][row] = __float2half(v4.z);
            Vts[lf4*4+3][row] = __float2half(v4.w);
        }
        __syncthreads();

        // S = Q K^T  (16 x 128 per warp)
        float sacc[16][4];
        #pragma unroll
        for (int ni=0;ni<16;ni++){ sacc[ni][0]=0.f; sacc[ni][1]=0.f; sacc[ni][2]=0.f; sacc[ni][3]=0.f; }
        #pragma unroll
        for (int s=0;s<4;s++){
            #pragma unroll
            for (int ni=0;ni<16;ni++){
                int n = ni*8 + g;
                uint32_t b0 = *(const uint32_t*)&Ks[n][s*16 + 2*tg];
                uint32_t b1 = *(const uint32_t*)&Ks[n][s*16 + 2*tg + 8];
                mma16816(sacc[ni], qf[s], b0, b1);
            }
        }

        // masking
        int s_k0   = (k0>=ck1)+(k0>=ck2);
        int s_k127 = (k0+127>=ck1)+(k0+127>=ck2);
        bool fullok = (k0+127 <= wlo) && (s_k0==sqa) && (s_k127==sqa) && (sqa==sqb);
        if (!fullok){
            #pragma unroll
            for (int ni=0;ni<16;ni++){
                int kg = k0 + ni*8 + 2*tg;
                int sk0 = (kg>=ck1)+(kg>=ck2);
                int sk1 = (kg+1>=ck1)+(kg+1>=ck2);
                if (!((kg   <= qg0) && (sk0==sq0))) sacc[ni][0] = -1e30f;
                if (!((kg+1 <= qg0) && (sk1==sq0))) sacc[ni][1] = -1e30f;
                if (!((kg   <= qg1) && (sk0==sq1))) sacc[ni][2] = -1e30f;
                if (!((kg+1 <= qg1) && (sk1==sq1))) sacc[ni][3] = -1e30f;
            }
        }

        // online softmax
        float tm0 = -1e20f, tm1 = -1e20f;
        #pragma unroll
        for (int ni=0;ni<16;ni++){
            tm0 = fmaxf(tm0, fmaxf(sacc[ni][0], sacc[ni][1]));
            tm1 = fmaxf(tm1, fmaxf(sacc[ni][2], sacc[ni][3]));
        }
        tm0 = fmaxf(tm0, __shfl_xor_sync(0xffffffffu, tm0, 1));
        tm0 = fmaxf(tm0, __shfl_xor_sync(0xffffffffu, tm0, 2));
        tm1 = fmaxf(tm1, __shfl_xor_sync(0xffffffffu, tm1, 1));
        tm1 = fmaxf(tm1, __shfl_xor_sync(0xffffffffu, tm1, 2));
        float mn0 = fmaxf(mr0, tm0), mn1 = fmaxf(mr1, tm1);
        float sc0 = __expf(mr0 - mn0), sc1 = __expf(mr1 - mn1);
        l0 *= sc0; l1 *= sc1;
        #pragma unroll
        for (int nd=0;nd<8;nd++){
            oacc[nd][0]*=sc0; oacc[nd][1]*=sc0; oacc[nd][2]*=sc1; oacc[nd][3]*=sc1;
        }
        uint32_t pf[8][4];
        float rs0 = 0.f, rs1 = 0.f;
        #pragma unroll
        for (int j=0;j<8;j++){
            float p00 = __expf(sacc[2*j][0]-mn0),   p01 = __expf(sacc[2*j][1]-mn0);
            float p10 = __expf(sacc[2*j][2]-mn1),   p11 = __expf(sacc[2*j][3]-mn1);
            float q00 = __expf(sacc[2*j+1][0]-mn0), q01 = __expf(sacc[2*j+1][1]-mn0);
            float q10 = __expf(sacc[2*j+1][2]-mn1), q11 = __expf(sacc[2*j+1][3]-mn1);
            rs0 += p00+p01+q00+q01;
            rs1 += p10+p11+q10+q11;
            pf[j][0] = packh2(p00,p01);
            pf[j][1] = packh2(p10,p11);
            pf[j][2] = packh2(q00,q01);
            pf[j][3] = packh2(q10,q11);
        }
        rs0 += __shfl_xor_sync(0xffffffffu, rs0, 1);
        rs0 += __shfl_xor_sync(0xffffffffu, rs0, 2);
        rs1 += __shfl_xor_sync(0xffffffffu, rs1, 1);
        rs1 += __shfl_xor_sync(0xffffffffu, rs1, 2);
        l0 += rs0; l1 += rs1;
        mr0 = mn0; mr1 = mn1;

        // O += P V
        #pragma unroll
        for (int j=0;j<8;j++){
            #pragma unroll
            for (int nd=0;nd<8;nd++){
                uint32_t b0 = *(const uint32_t*)&Vts[nd*8+g][16*j + 2*tg];
                uint32_t b1 = *(const uint32_t*)&Vts[nd*8+g][16*j + 2*tg + 8];
                mma16816(oacc[nd], pf[j], b0, b1);
            }
        }
    }

    float inv0 = (l0 > 0.f) ? 1.f/l0 : 0.f;
    float inv1 = (l1 > 0.f) ? 1.f/l1 : 0.f;
    float* or0 = o + ((size_t)(b*QLEN + qg0))*HIDDEN + h*HD;
    float* or1 = o + ((size_t)(b*QLEN + qg1))*HIDDEN + h*HD;
    #pragma unroll
    for (int nd=0;nd<8;nd++){
        int c = nd*8 + 2*tg;
        *(float2*)&or0[c] = make_float2(oacc[nd][0]*inv0, oacc[nd][1]*inv0);
        *(float2*)&or1[c] = make_float2(oacc[nd][2]*inv1, oacc[nd][3]*inv1);
    }
}

// ---------------- launch ----------------
extern "C" void kernel_launch(void* const* d_in, const int* in_sizes, int n_in,
                              void* d_out, int out_size)
{
    const float* hs   = (const float*)d_in[0];
    const float* kst  = (const float*)d_in[1];
    const float* vst  = (const float*)d_in[2];
    const float* wln1 = (const float*)d_in[4];
    const float* wln2 = (const float*)d_in[5];
    const float* wq   = (const float*)d_in[6];
    const float* wo   = (const float*)d_in[7];
    const float* wg   = (const float*)d_in[8];
    const float* wu   = (const float*)d_in[9];
    const float* wd   = (const float*)d_in[10];
    const int*   cuq  = (const int*)d_in[11];
    const int*   cuk  = (const int*)d_in[12];
    float* out = (float*)d_out;

    float *nrm,*qb,*attn,*hid,*nrm2,*gate;
    cudaGetSymbolAddress((void**)&nrm,  g_normed);
    cudaGetSymbolAddress((void**)&qb,   g_q);
    cudaGetSymbolAddress((void**)&attn, g_attn);
    cudaGetSymbolAddress((void**)&hid,  g_hidden);
    cudaGetSymbolAddress((void**)&nrm2, g_normed2);
    cudaGetSymbolAddress((void**)&gate, g_gate);

    // 1. RMSNorm1
    rmsnorm_k<<<MTOT, 256>>>(hs, wln1, nrm);

    // 2. Q = normed @ wq^T
    gemm_h<<<dim3(HIDDEN/128, MTOT/128), 256>>>(nrm, wq, qb, nullptr, MTOT, HIDDEN, HIDDEN, 0);

    // 3. fused flash attention
    flash_attn<<<dim3(QLEN/128, BATCH*NHEADS), 256>>>(qb, kst, vst, attn, cuq, cuk);

    // 4. hidden = residual + attn @ wo^T
    gemm_h<<<dim3(HIDDEN/128, MTOT/128), 256>>>(attn, wo, hid, hs, MTOT, HIDDEN, HIDDEN, 1);

    // 5. RMSNorm2
    rmsnorm_k<<<MTOT, 256>>>(hid, wln2, nrm2);

    // 6. gate = normed2 @ wg^T
    gemm_h<<<dim3(INTER/128, MTOT/128), 256>>>(nrm2, wg, gate, nullptr, MTOT, INTER, HIDDEN, 0);

    // 7. act = silu(gate) * (normed2 @ wu^T)   (written into gate)
    gemm_h<<<dim3(INTER/128, MTOT/128), 256>>>(nrm2, wu, gate, gate, MTOT, INTER, HIDDEN, 2);

    // 8. out = hidden + act @ wd^T
    gemm_h<<<dim3(HIDDEN/128, MTOT/128), 256>>>(gate, wd, out, hid, MTOT, HIDDEN, INTER, 1);
}

// round 3
// speedup vs baseline: 4.2453x; 1.4629x over previous
#include <cuda_runtime.h>
#include <cuda_fp16.h>
#include <cstdint>
#include <math.h>

#define HIDDEN 2048
#define NHEADS 32
#define NKV    8
#define HD     64
#define INTER  8192
#define BATCH  2
#define QLEN   2048
#define KLEN   2048
#define MTOT   (BATCH*QLEN)

// ---------------- scratch ----------------
__device__ __half g_wqh[(size_t)HIDDEN*HIDDEN];
__device__ __half g_woh[(size_t)HIDDEN*HIDDEN];
__device__ __half g_wgh[(size_t)INTER*HIDDEN];
__device__ __half g_wuh[(size_t)INTER*HIDDEN];
__device__ __half g_wdh[(size_t)HIDDEN*INTER];
__device__ __half g_kh [(size_t)BATCH*NKV*KLEN*HD];
__device__ __half g_vh [(size_t)BATCH*NKV*KLEN*HD];
__device__ __half g_n1h[(size_t)MTOT*HIDDEN];
__device__ __half g_qh [(size_t)MTOT*HIDDEN];
__device__ __half g_ath[(size_t)MTOT*HIDDEN];
__device__ __half g_n2h[(size_t)MTOT*HIDDEN];
__device__ __half g_gth[(size_t)MTOT*INTER];
__device__ __half g_ach[(size_t)MTOT*INTER];
__device__ float  g_hid[(size_t)MTOT*HIDDEN];

// ---------------- asm helpers ----------------
#define CPA(dst, src) asm volatile("cp.async.cg.shared.global [%0], [%1], 16;\n" :: "r"(dst), "l"(src))
#define CPC() asm volatile("cp.async.commit_group;\n")
#define CPW(N) asm volatile("cp.async.wait_group %0;\n" :: "n"(N))
#define LDSM4(r0,r1,r2,r3,addr) asm volatile("ldmatrix.sync.aligned.m8n8.x4.shared.b16 {%0,%1,%2,%3}, [%4];\n" \
    : "=r"(r0),"=r"(r1),"=r"(r2),"=r"(r3) : "r"(addr))
#define LDSM4T(r0,r1,r2,r3,addr) asm volatile("ldmatrix.sync.aligned.m8n8.x4.trans.shared.b16 {%0,%1,%2,%3}, [%4];\n" \
    : "=r"(r0),"=r"(r1),"=r"(r2),"=r"(r3) : "r"(addr))

__device__ __forceinline__ uint32_t packh2(float a, float b){
    __half2 h = __floats2half2_rn(a, b);
    return *reinterpret_cast<uint32_t*>(&h);
}
__device__ __forceinline__ void mma16816(float* c, const uint32_t* a, uint32_t b0, uint32_t b1){
    asm volatile("mma.sync.aligned.m16n8k16.row.col.f32.f16.f16.f32 "
        "{%0,%1,%2,%3}, {%4,%5,%6,%7}, {%8,%9}, {%0,%1,%2,%3};"
        : "+f"(c[0]), "+f"(c[1]), "+f"(c[2]), "+f"(c[3])
        : "r"(a[0]), "r"(a[1]), "r"(a[2]), "r"(a[3]), "r"(b0), "r"(b1));
}
__device__ __forceinline__ float blockSum(float v){
    __shared__ float sh[8];
    __shared__ float res;
    int lane = threadIdx.x & 31, w = threadIdx.x >> 5;
    #pragma unroll
    for (int o=16;o;o>>=1) v += __shfl_xor_sync(0xffffffffu, v, o);
    if (lane==0) sh[w] = v;
    __syncthreads();
    if (w==0){
        float x = (lane < 8) ? sh[lane] : 0.f;
        #pragma unroll
        for (int o=4;o;o>>=1) x += __shfl_xor_sync(0xffffffffu, x, o);
        if (lane==0) res = x;
    }
    __syncthreads();
    return res;
}

// ---------------- converts ----------------
__global__ void f2h4(const float* __restrict__ s, __half* __restrict__ d, int n){
    int i = (blockIdx.x*256 + threadIdx.x)*4;
    if (i < n){
        float4 v = *(const float4*)(s+i);
        *(__half2*)(d+i)   = __floats2half2_rn(v.x, v.y);
        *(__half2*)(d+i+2) = __floats2half2_rn(v.z, v.w);
    }
}
__global__ void convkv(const float* __restrict__ k, const float* __restrict__ v,
                       __half* __restrict__ kd, __half* __restrict__ vd){
    int idx = blockIdx.x*256 + threadIdx.x;          // over B*KLEN*NKV*(HD/2)
    if (idx >= BATCH*KLEN*NKV*(HD/2)) return;
    int d2  = idx & 31;
    int kvh = (idx>>5) & 7;
    int kk  = (idx>>8) & 2047;
    int bb  = idx>>19;
    size_t src = (((size_t)(bb*KLEN+kk)*NKV + kvh)*HD) + d2*2;
    size_t dst = (((size_t)(bb*NKV+kvh)*KLEN + kk)*HD) + d2*2;
    float2 kf = *(const float2*)(k+src);
    float2 vf = *(const float2*)(v+src);
    *(__half2*)(kd+dst) = __floats2half2_rn(kf.x, kf.y);
    *(__half2*)(vd+dst) = __floats2half2_rn(vf.x, vf.y);
}

// ---------------- RMSNorm (fp32 in, fp16 out) ----------------
__global__ void rmsnorm_h(const float* __restrict__ x, const float* __restrict__ w,
                          __half* __restrict__ o)
{
    size_t row = blockIdx.x;
    const float* xr = x + row*HIDDEN;
    __half* orow = o + row*HIDDEN;
    float s = 0.f;
    for (int i=threadIdx.x; i<HIDDEN; i+=256){ float v = xr[i]; s += v*v; }
    s = blockSum(s);
    float rs = rsqrtf(s*(1.f/HIDDEN) + 1e-5f);
    for (int i=threadIdx.x; i<HIDDEN; i+=256) orow[i] = __float2half(xr[i]*rs*w[i]);
}

// ---------------- fp16 GEMM: C[M,N] = A[M,K] @ B[N,K]^T ----------------
// mode 0: Ch = acc; 1: Cf = acc + Resf; 2: Ch = silu(Resh)*acc; 3: Ch = acc*0.125
#define SPITCH 72
#define STAGEB (128*SPITCH*2)   // bytes per stage per matrix

__global__ __launch_bounds__(256,2)
void gemm16(const __half* __restrict__ A, const __half* __restrict__ B,
            float* __restrict__ Cf, __half* __restrict__ Ch,
            const __half* __restrict__ Resh, const float* __restrict__ Resf,
            int M, int N, int K, int mode)
{
    extern __shared__ __half sm[];
    uint32_t asBase = (uint32_t)__cvta_generic_to_shared(sm);
    uint32_t bsBase = asBase + 2*STAGEB;

    const int tid = threadIdx.x, lane = tid&31, warp = tid>>5;
    const int g = lane>>2, tg = lane&3;
    const int wm = (warp&1)*64, wn = (warp>>1)*32;
    const int m0 = blockIdx.y*128, n0 = blockIdx.x*128;

    const int crow = tid>>3;      // 0..31 (+32*i)
    const int cchk = tid&7;       // 16B chunk within 128B row-slab
    const uint32_t sOff = (uint32_t)(crow*SPITCH*2 + cchk*16);
    const __half* aSrc = A + (size_t)(m0+crow)*K + cchk*8;
    const __half* bSrc = B + (size_t)(n0+crow)*K + cchk*8;

    float acc[4][4][4];
    #pragma unroll
    for (int i=0;i<4;i++)
        #pragma unroll
        for (int j=0;j<4;j++){ acc[i][j][0]=0.f; acc[i][j][1]=0.f; acc[i][j][2]=0.f; acc[i][j][3]=0.f; }

    const int nkb = K >> 6;

    // prologue
    {
        uint32_t ao = asBase + sOff, bo = bsBase + sOff;
        #pragma unroll
        for (int i=0;i<4;i++){
            CPA(ao + i*32*SPITCH*2, aSrc + (size_t)i*32*K);
            CPA(bo + i*32*SPITCH*2, bSrc + (size_t)i*32*K);
        }
        CPC();
    }

    for (int kb=0; kb<nkb; kb++){
        const int st = kb & 1;
        if (kb+1 < nkb){
            uint32_t ao = asBase + (st^1)*STAGEB + sOff;
            uint32_t bo = bsBase + (st^1)*STAGEB + sOff;
            const __half* ap = aSrc + (size_t)(kb+1)*64;
            const __half* bp = bSrc + (size_t)(kb+1)*64;
            #pragma unroll
            for (int i=0;i<4;i++){
                CPA(ao + i*32*SPITCH*2, ap + (size_t)i*32*K);
                CPA(bo + i*32*SPITCH*2, bp + (size_t)i*32*K);
            }
            CPC();
            CPW(1);
        } else {
            CPW(0);
        }
        __syncthreads();

        const uint32_t aW = asBase + st*STAGEB;
        const uint32_t bW = bsBase + st*STAGEB;
        #pragma unroll
        for (int kc=0;kc<4;kc++){
            uint32_t af[4][4], bf[2][4];
            #pragma unroll
            for (int mi=0;mi<4;mi++){
                int r = wm + mi*16 + (lane&15);
                int c = kc*16 + (lane>>4)*8;
                LDSM4(af[mi][0],af[mi][1],af[mi][2],af[mi][3], aW + (uint32_t)(r*SPITCH + c)*2);
            }
            #pragma unroll
            for (int nj=0;nj<2;nj++){
                int r = wn + nj*16 + (lane>>4)*8 + (lane&7);
                int c = kc*16 + ((lane>>3)&1)*8;
                LDSM4(bf[nj][0],bf[nj][1],bf[nj][2],bf[nj][3], bW + (uint32_t)(r*SPITCH + c)*2);
            }
            #pragma unroll
            for (int mi=0;mi<4;mi++){
                #pragma unroll
                for (int nj=0;nj<2;nj++){
                    mma16816(acc[mi][2*nj  ], af[mi], bf[nj][0], bf[nj][1]);
                    mma16816(acc[mi][2*nj+1], af[mi], bf[nj][2], bf[nj][3]);
                }
            }
        }
        __syncthreads();
    }

    // epilogue
    #pragma unroll
    for (int mi=0;mi<4;mi++){
        #pragma unroll
        for (int ni=0;ni<4;ni++){
            int r0 = m0 + wm + mi*16 + g;
            int r1 = r0 + 8;
            int c  = n0 + wn + ni*8 + 2*tg;
            size_t o0 = (size_t)r0*N + c;
            size_t o1 = (size_t)r1*N + c;
            float v0=acc[mi][ni][0], v1=acc[mi][ni][1], v2=acc[mi][ni][2], v3=acc[mi][ni][3];
            if (mode == 1){
                v0 += Resf[o0]; v1 += Resf[o0+1]; v2 += Resf[o1]; v3 += Resf[o1+1];
                *(float2*)&Cf[o0] = make_float2(v0,v1);
                *(float2*)&Cf[o1] = make_float2(v2,v3);
            } else if (mode == 2){
                float g0 = __half2float(Resh[o0]), g1 = __half2float(Resh[o0+1]);
                float g2 = __half2float(Resh[o1]), g3 = __half2float(Resh[o1+1]);
                v0 *= g0/(1.f+__expf(-g0)); v1 *= g1/(1.f+__expf(-g1));
                v2 *= g2/(1.f+__expf(-g2)); v3 *= g3/(1.f+__expf(-g3));
                *(__half2*)&Ch[o0] = __floats2half2_rn(v0,v1);
                *(__half2*)&Ch[o1] = __floats2half2_rn(v2,v3);
            } else if (mode == 3){
                *(__half2*)&Ch[o0] = __floats2half2_rn(v0*0.125f, v1*0.125f);
                *(__half2*)&Ch[o1] = __floats2half2_rn(v2*0.125f, v3*0.125f);
            } else {
                *(__half2*)&Ch[o0] = __floats2half2_rn(v0,v1);
                *(__half2*)&Ch[o1] = __floats2half2_rn(v2,v3);
            }
        }
    }
}

// ---------------- flash attention v3 (cp.async + ldmatrix) ----------------
__global__ __launch_bounds__(256,1)
void flash3(const __half* __restrict__ qh, const __half* __restrict__ kh,
            const __half* __restrict__ vh, __half* __restrict__ oh,
            const int* __restrict__ cuq, const int* __restrict__ cuk)
{
    extern __shared__ __half sm[];
    uint32_t ksBase = (uint32_t)__cvta_generic_to_shared(sm);
    uint32_t vsBase = ksBase + 2*STAGEB;

    const int tid  = threadIdx.x;
    const int lane = tid & 31, warp = tid >> 5;
    const int g = lane >> 2, tg = lane & 3;
    const int bh = blockIdx.y;
    const int b = bh >> 5, h = bh & 31, kv = h >> 2;
    const int q0 = blockIdx.x * 128;
    const int wq = warp * 16;

    const int cq1 = cuq[1], cq2 = cuq[2];
    const int ck1 = cuk[1], ck2 = cuk[2];

    const int qg0 = q0 + wq + g, qg1 = qg0 + 8;
    const __half* qr0 = qh + ((size_t)(b*QLEN + qg0))*HIDDEN + h*HD;
    const __half* qr1 = qh + ((size_t)(b*QLEN + qg1))*HIDDEN + h*HD;
    uint32_t qf[4][4];
    #pragma unroll
    for (int kc=0;kc<4;kc++){
        qf[kc][0] = *(const uint32_t*)(qr0 + kc*16 + 2*tg);
        qf[kc][1] = *(const uint32_t*)(qr1 + kc*16 + 2*tg);
        qf[kc][2] = *(const uint32_t*)(qr0 + kc*16 + 2*tg + 8);
        qf[kc][3] = *(const uint32_t*)(qr1 + kc*16 + 2*tg + 8);
    }

    const int sq0 = (qg0>=cq1)+(qg0>=cq2);
    const int sq1 = (qg1>=cq1)+(qg1>=cq2);
    const int wlo = q0 + wq, whi = wlo + 15;
    const int sqa = (wlo>=cq1)+(wlo>=cq2);
    const int sqb = (whi>=cq1)+(whi>=cq2);

    float oacc[8][4];
    #pragma unroll
    for (int i=0;i<8;i++){ oacc[i][0]=0.f; oacc[i][1]=0.f; oacc[i][2]=0.f; oacc[i][3]=0.f; }
    float mr0 = -1e20f, mr1 = -1e20f, l0 = 0.f, l1 = 0.f;

    int segA = (q0>=cq1)+(q0>=cq2);
    int segB = (q0+127>=cq1)+(q0+127>=cq2);
    int klo, khi;
    if (segA == segB){
        int klos = (segA==0) ? 0 : ((segA==1) ? ck1 : ck2);
        int khis = (segA==0) ? ck1 : ((segA==1) ? ck2 : KLEN);
        klo = klos;
        khi = min(khis, q0+128);
    } else { klo = 0; khi = q0+128; }
    const int t0 = klo >> 7, t1 = (khi + 127) >> 7;

    const __half* kBase = kh + (size_t)(b*NKV+kv)*KLEN*HD;
    const __half* vBase = vh + (size_t)(b*NKV+kv)*KLEN*HD;
    const int crow = tid>>3, cchk = tid&7;
    const uint32_t sOff = (uint32_t)(crow*SPITCH*2 + cchk*16);

    // prologue: load tile t0 into stage 0
    {
        uint32_t ko = ksBase + sOff, vo = vsBase + sOff;
        const __half* kp = kBase + (size_t)(t0*128 + crow)*HD + cchk*8;
        const __half* vp = vBase + (size_t)(t0*128 + crow)*HD + cchk*8;
        #pragma unroll
        for (int i=0;i<4;i++){
            CPA(ko + i*32*SPITCH*2, kp + (size_t)i*32*HD);
            CPA(vo + i*32*SPITCH*2, vp + (size_t)i*32*HD);
        }
        CPC();
    }

    for (int t=t0; t<t1; t++){
        const int st = (t - t0) & 1;
        const int k0 = t << 7;
        if (t+1 < t1){
            uint32_t ko = ksBase + (st^1)*STAGEB + sOff;
            uint32_t vo = vsBase + (st^1)*STAGEB + sOff;
            const __half* kp = kBase + (size_t)((t+1)*128 + crow)*HD + cchk*8;
            const __half* vp = vBase + (size_t)((t+1)*128 + crow)*HD + cchk*8;
            #pragma unroll
            for (int i=0;i<4;i++){
                CPA(ko + i*32*SPITCH*2, kp + (size_t)i*32*HD);
                CPA(vo + i*32*SPITCH*2, vp + (size_t)i*32*HD);
            }
            CPC();
            CPW(1);
        } else {
            CPW(0);
        }
        __syncthreads();

        const uint32_t kW = ksBase + st*STAGEB;
        const uint32_t vW = vsBase + st*STAGEB;

        // S = Q K^T
        float sacc[16][4];
        #pragma unroll
        for (int ni=0;ni<16;ni++){ sacc[ni][0]=0.f; sacc[ni][1]=0.f; sacc[ni][2]=0.f; sacc[ni][3]=0.f; }
        #pragma unroll
        for (int kc=0;kc<4;kc++){
            #pragma unroll
            for (int nj=0;nj<8;nj++){
                uint32_t b0,b1,b2,b3;
                int r = nj*16 + (lane>>4)*8 + (lane&7);
                int c = kc*16 + ((lane>>3)&1)*8;
                LDSM4(b0,b1,b2,b3, kW + (uint32_t)(r*SPITCH + c)*2);
                mma16816(sacc[2*nj  ], qf[kc], b0, b1);
                mma16816(sacc[2*nj+1], qf[kc], b2, b3);
            }
        }

        // masking
        int s_k0   = (k0>=ck1)+(k0>=ck2);
        int s_k127 = (k0+127>=ck1)+(k0+127>=ck2);
        bool fullok = (k0+127 <= wlo) && (s_k0==sqa) && (s_k127==sqa) && (sqa==sqb);
        if (!fullok){
            #pragma unroll
            for (int ni=0;ni<16;ni++){
                int kg = k0 + ni*8 + 2*tg;
                int sk0 = (kg>=ck1)+(kg>=ck2);
                int sk1 = (kg+1>=ck1)+(kg+1>=ck2);
                if (!((kg   <= qg0) && (sk0==sq0))) sacc[ni][0] = -1e30f;
                if (!((kg+1 <= qg0) && (sk1==sq0))) sacc[ni][1] = -1e30f;
                if (!((kg   <= qg1) && (sk0==sq1))) sacc[ni][2] = -1e30f;
                if (!((kg+1 <= qg1) && (sk1==sq1))) sacc[ni][3] = -1e30f;
            }
        }

        // online softmax
        float tm0 = -1e20f, tm1 = -1e20f;
        #pragma unroll
        for (int ni=0;ni<16;ni++){
            tm0 = fmaxf(tm0, fmaxf(sacc[ni][0], sacc[ni][1]));
            tm1 = fmaxf(tm1, fmaxf(sacc[ni][2], sacc[ni][3]));
        }
        tm0 = fmaxf(tm0, __shfl_xor_sync(0xffffffffu, tm0, 1));
        tm0 = fmaxf(tm0, __shfl_xor_sync(0xffffffffu, tm0, 2));
        tm1 = fmaxf(tm1, __shfl_xor_sync(0xffffffffu, tm1, 1));
        tm1 = fmaxf(tm1, __shfl_xor_sync(0xffffffffu, tm1, 2));
        float mn0 = fmaxf(mr0, tm0), mn1 = fmaxf(mr1, tm1);
        float sc0 = __expf(mr0 - mn0), sc1 = __expf(mr1 - mn1);
        l0 *= sc0; l1 *= sc1;
        #pragma unroll
        for (int nd=0;nd<8;nd++){
            oacc[nd][0]*=sc0; oacc[nd][1]*=sc0; oacc[nd][2]*=sc1; oacc[nd][3]*=sc1;
        }
        uint32_t pf[8][4];
        float rs0 = 0.f, rs1 = 0.f;
        #pragma unroll
        for (int j=0;j<8;j++){
            float p00 = __expf(sacc[2*j][0]-mn0),   p01 = __expf(sacc[2*j][1]-mn0);
            float p10 = __expf(sacc[2*j][2]-mn1),   p11 = __expf(sacc[2*j][3]-mn1);
            float q00 = __expf(sacc[2*j+1][0]-mn0), q01 = __expf(sacc[2*j+1][1]-mn0);
            float q10 = __expf(sacc[2*j+1][2]-mn1), q11 = __expf(sacc[2*j+1][3]-mn1);
            rs0 += p00+p01+q00+q01;
            rs1 += p10+p11+q10+q11;
            pf[j][0] = packh2(p00,p01);
            pf[j][1] = packh2(p10,p11);
            pf[j][2] = packh2(q00,q01);
            pf[j][3] = packh2(q10,q11);
        }
        rs0 += __shfl_xor_sync(0xffffffffu, rs0, 1);
        rs0 += __shfl_xor_sync(0xffffffffu, rs0, 2);
        rs1 += __shfl_xor_sync(0xffffffffu, rs1, 1);
        rs1 += __shfl_xor_sync(0xffffffffu, rs1, 2);
        l0 += rs0; l1 += rs1;
        mr0 = mn0; mr1 = mn1;

        // O += P V  (V fragments via ldmatrix.trans)
        #pragma unroll
        for (int j=0;j<8;j++){
            #pragma unroll
            for (int dq=0;dq<4;dq++){
                uint32_t b0,b1,b2,b3;
                int r = j*16 + ((lane>>3)&1)*8 + (lane&7);
                int c = dq*16 + (lane>>4)*8;
                LDSM4T(b0,b1,b2,b3, vW + (uint32_t)(r*SPITCH + c)*2);
                mma16816(oacc[2*dq  ], pf[j], b0, b1);
                mma16816(oacc[2*dq+1], pf[j], b2, b3);
            }
        }
        __syncthreads();
    }

    float inv0 = (l0 > 0.f) ? 1.f/l0 : 0.f;
    float inv1 = (l1 > 0.f) ? 1.f/l1 : 0.f;
    __half* or0 = oh + ((size_t)(b*QLEN + qg0))*HIDDEN + h*HD;
    __half* or1 = oh + ((size_t)(b*QLEN + qg1))*HIDDEN + h*HD;
    #pragma unroll
    for (int nd=0;nd<8;nd++){
        int c = nd*8 + 2*tg;
        *(__half2*)&or0[c] = __floats2half2_rn(oacc[nd][0]*inv0, oacc[nd][1]*inv0);
        *(__half2*)&or1[c] = __floats2half2_rn(oacc[nd][2]*inv1, oacc[nd][3]*inv1);
    }
}

// ---------------- launch ----------------
extern "C" void kernel_launch(void* const* d_in, const int* in_sizes, int n_in,
                              void* d_out, int out_size)
{
    const float* hs   = (const float*)d_in[0];
    const float* kst  = (const float*)d_in[1];
    const float* vst  = (const float*)d_in[2];
    const float* wln1 = (const float*)d_in[4];
    const float* wln2 = (const float*)d_in[5];
    const float* wq   = (const float*)d_in[6];
    const float* wo   = (const float*)d_in[7];
    const float* wg   = (const float*)d_in[8];
    const float* wu   = (const float*)d_in[9];
    const float* wd   = (const float*)d_in[10];
    const int*   cuq  = (const int*)d_in[11];
    const int*   cuk  = (const int*)d_in[12];
    float* out = (float*)d_out;

    __half *wqh,*woh,*wgh,*wuh,*wdh,*kh,*vh,*n1h,*qh,*ath,*n2h,*gth,*ach;
    float *hid;
    cudaGetSymbolAddress((void**)&wqh, g_wqh);
    cudaGetSymbolAddress((void**)&woh, g_woh);
    cudaGetSymbolAddress((void**)&wgh, g_wgh);
    cudaGetSymbolAddress((void**)&wuh, g_wuh);
    cudaGetSymbolAddress((void**)&wdh, g_wdh);
    cudaGetSymbolAddress((void**)&kh,  g_kh);
    cudaGetSymbolAddress((void**)&vh,  g_vh);
    cudaGetSymbolAddress((void**)&n1h, g_n1h);
    cudaGetSymbolAddress((void**)&qh,  g_qh);
    cudaGetSymbolAddress((void**)&ath, g_ath);
    cudaGetSymbolAddress((void**)&n2h, g_n2h);
    cudaGetSymbolAddress((void**)&gth, g_gth);
    cudaGetSymbolAddress((void**)&ach, g_ach);
    cudaGetSymbolAddress((void**)&hid, g_hid);

    const int SMEM = 4*STAGEB;  // 73728 bytes
    cudaFuncSetAttribute(gemm16, cudaFuncAttributeMaxDynamicSharedMemorySize, SMEM);
    cudaFuncSetAttribute(flash3, cudaFuncAttributeMaxDynamicSharedMemorySize, SMEM);

    // weight / kv converts
    const int HH = HIDDEN*HIDDEN, IH = INTER*HIDDEN;
    f2h4<<<(HH/4+255)/256, 256>>>(wq, wqh, HH);
    f2h4<<<(HH/4+255)/256, 256>>>(wo, woh, HH);
    f2h4<<<(IH/4+255)/256, 256>>>(wg, wgh, IH);
    f2h4<<<(IH/4+255)/256, 256>>>(wu, wuh, IH);
    f2h4<<<(IH/4+255)/256, 256>>>(wd, wdh, IH);
    convkv<<<(BATCH*KLEN*NKV*(HD/2)+255)/256, 256>>>(kst, vst, kh, vh);

    // 1. RMSNorm1 -> fp16
    rmsnorm_h<<<MTOT, 256>>>(hs, wln1, n1h);

    // 2. Q = normed @ wq^T, scaled 0.125, fp16
    gemm16<<<dim3(HIDDEN/128, MTOT/128), 256, SMEM>>>(n1h, wqh, nullptr, qh, nullptr, nullptr, MTOT, HIDDEN, HIDDEN, 3);

    // 3. flash attention -> fp16
    flash3<<<dim3(QLEN/128, BATCH*NHEADS), 256, SMEM>>>(qh, kh, vh, ath, cuq, cuk);

    // 4. hidden = residual + attn @ wo^T (fp32)
    gemm16<<<dim3(HIDDEN/128, MTOT/128), 256, SMEM>>>(ath, woh, hid, nullptr, nullptr, hs, MTOT, HIDDEN, HIDDEN, 1);

    // 5. RMSNorm2 -> fp16
    rmsnorm_h<<<MTOT, 256>>>(hid, wln2, n2h);

    // 6. gate = normed2 @ wg^T (fp16)
    gemm16<<<dim3(INTER/128, MTOT/128), 256, SMEM>>>(n2h, wgh, nullptr, gth, nullptr, nullptr, MTOT, INTER, HIDDEN, 0);

    // 7. act = silu(gate) * (normed2 @ wu^T) (fp16)
    gemm16<<<dim3(INTER/128, MTOT/128), 256, SMEM>>>(n2h, wuh, nullptr, ach, gth, nullptr, MTOT, INTER, HIDDEN, 2);

    // 8. out = hidden + act @ wd^T (fp32)
    gemm16<<<dim3(HIDDEN/128, MTOT/128), 256, SMEM>>>(ach, wdh, out, nullptr, nullptr, hid, MTOT, HIDDEN, INTER, 1);
}

// round 5
// speedup vs baseline: 7.9065x; 1.8624x over previous
#include <cuda_runtime.h>
#include <cuda_fp16.h>
#include <cstdint>
#include <math.h>

#define HIDDEN 2048
#define NHEADS 32
#define NKV    8
#define HD     64
#define INTER  8192
#define BATCH  2
#define QLEN   2048
#define KLEN   2048
#define MTOT   (BATCH*QLEN)

// Does this device compilation pass support tcgen05?
#if defined(__CUDA_ARCH_FEAT_SM103_ALL) || defined(__CUDA_ARCH_FEAT_SM100_ALL)
#define HAS_TCGEN05 1
#else
#define HAS_TCGEN05 0
#endif

// ---------------- scratch ----------------
__device__ __half g_wqh[(size_t)HIDDEN*HIDDEN];
__device__ __half g_woh[(size_t)HIDDEN*HIDDEN];
__device__ __half g_wgh[(size_t)INTER*HIDDEN];
__device__ __half g_wuh[(size_t)INTER*HIDDEN];
__device__ __half g_wdh[(size_t)HIDDEN*INTER];
__device__ __half g_kh [(size_t)BATCH*NKV*KLEN*HD];
__device__ __half g_vh [(size_t)BATCH*NKV*KLEN*HD];
__device__ __half g_n1h[(size_t)MTOT*HIDDEN];
__device__ __half g_qh [(size_t)MTOT*HIDDEN];
__device__ __half g_ath[(size_t)MTOT*HIDDEN];
__device__ __half g_n2h[(size_t)MTOT*HIDDEN];
__device__ __half g_gth[(size_t)MTOT*INTER];
__device__ __half g_ach[(size_t)MTOT*INTER];
__device__ float  g_hid[(size_t)MTOT*HIDDEN];

// ---------------- asm helpers ----------------
#define CPA(dst, src) asm volatile("cp.async.cg.shared.global [%0], [%1], 16;\n" :: "r"(dst), "l"(src))
#define CPC() asm volatile("cp.async.commit_group;\n")
#define CPW(N) asm volatile("cp.async.wait_group %0;\n" :: "n"(N))
#define LDSM4(r0,r1,r2,r3,addr) asm volatile("ldmatrix.sync.aligned.m8n8.x4.shared.b16 {%0,%1,%2,%3}, [%4];\n" \
    : "=r"(r0),"=r"(r1),"=r"(r2),"=r"(r3) : "r"(addr))
#define LDSM4T(r0,r1,r2,r3,addr) asm volatile("ldmatrix.sync.aligned.m8n8.x4.trans.shared.b16 {%0,%1,%2,%3}, [%4];\n" \
    : "=r"(r0),"=r"(r1),"=r"(r2),"=r"(r3) : "r"(addr))

__device__ __forceinline__ uint32_t packh2(float a, float b){
    __half2 h = __floats2half2_rn(a, b);
    return *reinterpret_cast<uint32_t*>(&h);
}
__device__ __forceinline__ void mma16816(float* c, const uint32_t* a, uint32_t b0, uint32_t b1){
    asm volatile("mma.sync.aligned.m16n8k16.row.col.f32.f16.f16.f32 "
        "{%0,%1,%2,%3}, {%4,%5,%6,%7}, {%8,%9}, {%0,%1,%2,%3};"
        : "+f"(c[0]), "+f"(c[1]), "+f"(c[2]), "+f"(c[3])
        : "r"(a[0]), "r"(a[1]), "r"(a[2]), "r"(a[3]), "r"(b0), "r"(b1));
}
__device__ __forceinline__ float blockSum(float v){
    __shared__ float sh[8];
    __shared__ float res;
    int lane = threadIdx.x & 31, w = threadIdx.x >> 5;
    #pragma unroll
    for (int o=16;o;o>>=1) v += __shfl_xor_sync(0xffffffffu, v, o);
    if (lane==0) sh[w] = v;
    __syncthreads();
    if (w==0){
        float x = (lane < 8) ? sh[lane] : 0.f;
        #pragma unroll
        for (int o=4;o;o>>=1) x += __shfl_xor_sync(0xffffffffu, x, o);
        if (lane==0) res = x;
    }
    __syncthreads();
    return res;
}

// ---------------- converts ----------------
__global__ void f2h4(const float* __restrict__ s, __half* __restrict__ d, int n){
    int i = (blockIdx.x*256 + threadIdx.x)*4;
    if (i < n){
        float4 v = *(const float4*)(s+i);
        *(__half2*)(d+i)   = __floats2half2_rn(v.x, v.y);
        *(__half2*)(d+i+2) = __floats2half2_rn(v.z, v.w);
    }
}
__global__ void convkv(const float* __restrict__ k, const float* __restrict__ v,
                       __half* __restrict__ kd, __half* __restrict__ vd){
    int idx = blockIdx.x*256 + threadIdx.x;
    if (idx >= BATCH*KLEN*NKV*(HD/2)) return;
    int d2  = idx & 31;
    int kvh = (idx>>5) & 7;
    int kk  = (idx>>8) & 2047;
    int bb  = idx>>19;
    size_t src = (((size_t)(bb*KLEN+kk)*NKV + kvh)*HD) + d2*2;
    size_t dst = (((size_t)(bb*NKV+kvh)*KLEN + kk)*HD) + d2*2;
    float2 kf = *(const float2*)(k+src);
    float2 vf = *(const float2*)(v+src);
    *(__half2*)(kd+dst) = __floats2half2_rn(kf.x, kf.y);
    *(__half2*)(vd+dst) = __floats2half2_rn(vf.x, vf.y);
}

// ---------------- RMSNorm ----------------
__global__ void rmsnorm_h(const float* __restrict__ x, const float* __restrict__ w,
                          __half* __restrict__ o)
{
    size_t row = blockIdx.x;
    const float* xr = x + row*HIDDEN;
    __half* orow = o + row*HIDDEN;
    float s = 0.f;
    for (int i=threadIdx.x; i<HIDDEN; i+=256){ float v = xr[i]; s += v*v; }
    s = blockSum(s);
    float rs = rsqrtf(s*(1.f/HIDDEN) + 1e-5f);
    for (int i=threadIdx.x; i<HIDDEN; i+=256) orow[i] = __float2half(xr[i]*rs*w[i]);
}

// ==================== tcgen05 GEMM (guarded) ====================
// CTA tile 256x256, two M=128/N=256 MMA streams into TMEM halves.
// mode 0: Ch=acc; 1: Cf=acc+Resf; 2: Ch=silu(Resh)*acc; 3: Ch=acc*0.125
#define TCSTAGE 65536
#define TC_SMEM (3*TCSTAGE + 2048)
#define EPITCH 33

#if HAS_TCGEN05
__device__ __forceinline__ uint32_t elect_one_pred(){
    uint32_t pred;
    asm volatile("{\n\t.reg .pred p;\n\telect.sync _|p, 0xFFFFFFFF;\n\tselp.b32 %0, 1, 0, p;\n\t}" : "=r"(pred));
    return pred;
}
#define MBARRIER_INIT(addr, cnt) \
    asm volatile("mbarrier.init.shared.b64 [%0], %1;" :: "r"((uint32_t)(addr)), "r"((uint32_t)(cnt)) : "memory")
__device__ __forceinline__ void mbar_wait(uint32_t mbar, uint32_t phase){
    asm volatile(
        "{\n\t.reg .pred P1;\n\t"
        "WAIT_%=:\n\t"
        "mbarrier.try_wait.parity.acquire.cta.shared::cta.b64 P1, [%0], %1, 0x989680;\n\t"
        "@P1 bra.uni DONE_%=;\n\t"
        "bra.uni WAIT_%=;\n\t"
        "DONE_%=:\n\t}"
        :: "r"(mbar), "r"(phase) : "memory");
}
static __device__ __forceinline__ uint64_t make_desc_sw128(uint32_t addr){
    const uint64_t base =
        (uint64_t(2)  << 61) | (uint64_t(1) << 46) | (uint64_t(64) << 32) | (uint64_t(1) << 16);
    return base | ((uint64_t)(addr >> 4) & 0x3FFF);
}
#define IDESC_F16 ((1u<<4) | (32u<<17) | (8u<<24))
__device__ __forceinline__ void mma_f16_ss(uint32_t d, uint64_t ad, uint64_t bd, uint32_t en){
    asm volatile(
        "{\n\t.reg .pred p;\n\tsetp.ne.u32 p, %5, 0;\n\t"
        "tcgen05.mma.cta_group::1.kind::f16 [%0], %1, %2, %3, {%4,%4,%4,%4}, p;\n\t}"
        :: "r"(d), "l"(ad), "l"(bd), "r"(IDESC_F16), "r"(0u), "r"(en) : "memory");
}
#endif

__global__ __launch_bounds__(256,1)
void gemm_tc(const __half* __restrict__ A, const __half* __restrict__ B,
             float* __restrict__ Cf, __half* __restrict__ Ch,
             const __half* __restrict__ Resh, const float* __restrict__ Resf,
             int M, int N, int K, int mode)
{
#if HAS_TCGEN05
    extern __shared__ char smraw[];
    uint32_t smem0 = (uint32_t)__cvta_generic_to_shared(smraw);
    uint32_t base  = (smem0 + 1023u) & ~1023u;
    char* gbase = smraw + (base - smem0);
    const uint32_t ctrl = base + 3*TCSTAGE;
    const uint32_t mb   = ctrl + 16;   // 4 mbarriers

    const int tid = threadIdx.x, lane = tid&31, warp = tid>>5;
    const int m0 = blockIdx.y*256, n0 = blockIdx.x*256;

    if (warp==0) TCGEN05_ALLOC_IMPL: ;
    if (warp==0)
        asm volatile("tcgen05.alloc.cta_group::1.sync.aligned.shared::cta.b32 [%0], %1;"
            :: "r"(ctrl), "r"(512u) : "memory");
    if (tid==0){
        #pragma unroll
        for (int i=0;i<4;i++) MBARRIER_INIT(mb + i*8, 1);
    }
    __syncthreads();
    uint32_t tmem; asm volatile("ld.shared.b32 %0, [%1];" : "=r"(tmem) : "r"(ctrl));

    const int nkb = K >> 6;
    const int off = tid & 7;
    const int rbase = tid >> 3;

    uint32_t aAddr[3], bAddr[3];
    uint64_t aDesc[3], bDesc[3];
    #pragma unroll
    for (int s=0;s<3;s++){
        aAddr[s] = base + s*TCSTAGE;
        bAddr[s] = base + s*TCSTAGE + 32768;
        aDesc[s] = make_desc_sw128(aAddr[s]);
        bDesc[s] = make_desc_sw128(bAddr[s]);
    }
    uint32_t swOff[8];
    #pragma unroll
    for (int i=0;i<8;i++){
        uint32_t bo = (uint32_t)((rbase + i*32)*128 + off*16);
        swOff[i] = bo ^ ((bo>>3)&0x70);
    }

    const __half* aTh = A + (size_t)m0*K + off*8;
    const __half* bTh = B + (size_t)n0*K + off*8;

    // prologue: chunks 0,1 into stages 0,1
    #pragma unroll
    for (int c=0;c<2;c++){
        const __half* ap = aTh + (size_t)c*64;
        const __half* bp = bTh + (size_t)c*64;
        #pragma unroll
        for (int i=0;i<8;i++){
            size_t ro = (size_t)(rbase + i*32)*K;
            CPA(aAddr[c] + swOff[i], ap + ro);
            CPA(bAddr[c] + swOff[i], bp + ro);
        }
        CPC();
    }

    for (int t=0; t<nkb; t++){
        const int st = t%3;
        if (t+2 < nkb){
            const int ls = (t+2)%3;
            if (t >= 1) mbar_wait(mb + ls*8, (uint32_t)(((t-1)/3)&1));
            const __half* ap = aTh + (size_t)(t+2)*64;
            const __half* bp = bTh + (size_t)(t+2)*64;
            #pragma unroll
            for (int i=0;i<8;i++){
                size_t ro = (size_t)(rbase + i*32)*K;
                CPA(aAddr[ls] + swOff[i], ap + ro);
                CPA(bAddr[ls] + swOff[i], bp + ro);
            }
            CPC();
            CPW(2);
        } else if (t+1 < nkb){
            CPW(1);
        } else {
            CPW(0);
        }
        __syncthreads();
        asm volatile("fence.proxy.async.shared::cta;" ::: "memory");
        if (warp==0){
            asm volatile("tcgen05.fence::after_thread_sync;" ::: "memory");
            if (elect_one_pred()){
                #pragma unroll
                for (int hf=0; hf<2; hf++){
                    #pragma unroll
                    for (int kc=0;kc<4;kc++){
                        mma_f16_ss(tmem + hf*256,
                                   aDesc[st] + hf*1024 + kc*2,
                                   bDesc[st] + kc*2,
                                   (t>0 || kc>0) ? 1u : 0u);
                    }
                }
                asm volatile("tcgen05.commit.cta_group::1.mbarrier::arrive::one.shared::cluster.b64 [%0];"
                    :: "r"(mb + (uint32_t)st*8) : "memory");
            }
        }
    }

    // final completion on mb[3]
    if (warp==0 && elect_one_pred())
        asm volatile("tcgen05.commit.cta_group::1.mbarrier::arrive::one.shared::cluster.b64 [%0];"
            :: "r"(mb + 24u) : "memory");
    mbar_wait(mb + 24, 0u);
    asm volatile("tcgen05.fence::after_thread_sync;" ::: "memory");
    __syncthreads();

    // epilogue: LDTM -> smem (pitch 33, conflict-free) -> coalesced gmem
    float* sEp = (float*)gbase;
    const int hf  = warp>>2;
    const int wsb = warp&3;
    const int rr = tid>>3, c4 = (tid&7)*4;

    for (int cc=0; cc<8; cc++){
        uint32_t r[32];
        asm volatile(
            "tcgen05.ld.sync.aligned.32x32b.x32.b32 "
            "{%0, %1, %2, %3, %4, %5, %6, %7, "
            " %8, %9, %10, %11, %12, %13, %14, %15, "
            " %16, %17, %18, %19, %20, %21, %22, %23, "
            " %24, %25, %26, %27, %28, %29, %30, %31}, [%32];"
            : "=r"(r[0]),  "=r"(r[1]),  "=r"(r[2]),  "=r"(r[3]),
              "=r"(r[4]),  "=r"(r[5]),  "=r"(r[6]),  "=r"(r[7]),
              "=r"(r[8]),  "=r"(r[9]),  "=r"(r[10]), "=r"(r[11]),
              "=r"(r[12]), "=r"(r[13]), "=r"(r[14]), "=r"(r[15]),
              "=r"(r[16]), "=r"(r[17]), "=r"(r[18]), "=r"(r[19]),
              "=r"(r[20]), "=r"(r[21]), "=r"(r[22]), "=r"(r[23]),
              "=r"(r[24]), "=r"(r[25]), "=r"(r[26]), "=r"(r[27]),
              "=r"(r[28]), "=r"(r[29]), "=r"(r[30]), "=r"(r[31])
            : "r"(tmem + hf*256 + cc*32));
        asm volatile("tcgen05.wait::ld.sync.aligned;" ::: "memory");
        float* sp = sEp + (hf*128 + wsb*32 + lane)*EPITCH;
        #pragma unroll
        for (int j=0;j<32;j++) sp[j] = __uint_as_float(r[j]);
        __syncthreads();
        #pragma unroll
        for (int i=0;i<8;i++){
            int row = i*32 + rr;
            size_t go = (size_t)(m0 + row)*N + (n0 + cc*32 + c4);
            const float* s4 = sEp + row*EPITCH + c4;
            float v0=s4[0], v1=s4[1], v2=s4[2], v3=s4[3];
            if (mode==1){
                float4 rf = *(const float4*)(Resf + go);
                *(float4*)(Cf + go) = make_float4(v0+rf.x, v1+rf.y, v2+rf.z, v3+rf.w);
            } else if (mode==2){
                uint2 rh = *(const uint2*)(Resh + go);
                __half2 h0 = *(__half2*)&rh.x, h1 = *(__half2*)&rh.y;
                float g0 = __half2float(h0.x), g1 = __half2float(h0.y);
                float g2 = __half2float(h1.x), g3 = __half2float(h1.y);
                v0 *= g0/(1.f+__expf(-g0)); v1 *= g1/(1.f+__expf(-g1));
                v2 *= g2/(1.f+__expf(-g2)); v3 *= g3/(1.f+__expf(-g3));
                *(uint2*)(Ch + go) = make_uint2(packh2(v0,v1), packh2(v2,v3));
            } else if (mode==3){
                *(uint2*)(Ch + go) = make_uint2(packh2(v0*0.125f, v1*0.125f),
                                                packh2(v2*0.125f, v3*0.125f));
            } else {
                *(uint2*)(Ch + go) = make_uint2(packh2(v0,v1), packh2(v2,v3));
            }
        }
        __syncthreads();
    }

    asm volatile("tcgen05.fence::before_thread_sync;" ::: "memory");
    __syncthreads();
    if (warp==0)
        asm volatile("tcgen05.dealloc.cta_group::1.sync.aligned.b32 %0, %1;" :: "r"(tmem), "r"(512u));
#endif
}

// ---------------- fallback fp16 mma.sync GEMM (proven R3) ----------------
#define SPITCH 72
#define STAGEB (128*SPITCH*2)

__global__ __launch_bounds__(256,2)
void gemm16(const __half* __restrict__ A, const __half* __restrict__ B,
            float* __restrict__ Cf, __half* __restrict__ Ch,
            const __half* __restrict__ Resh, const float* __restrict__ Resf,
            int M, int N, int K, int mode)
{
    extern __shared__ __half smf[];
    uint32_t asBase = (uint32_t)__cvta_generic_to_shared(smf);
    uint32_t bsBase = asBase + 2*STAGEB;

    const int tid = threadIdx.x, lane = tid&31, warp = tid>>5;
    const int g = lane>>2, tg = lane&3;
    const int wm = (warp&1)*64, wn = (warp>>1)*32;
    const int m0 = blockIdx.y*128, n0 = blockIdx.x*128;

    const int crow = tid>>3;
    const int cchk = tid&7;
    const uint32_t sOff = (uint32_t)(crow*SPITCH*2 + cchk*16);
    const __half* aSrc = A + (size_t)(m0+crow)*K + cchk*8;
    const __half* bSrc = B + (size_t)(n0+crow)*K + cchk*8;

    float acc[4][4][4];
    #pragma unroll
    for (int i=0;i<4;i++)
        #pragma unroll
        for (int j=0;j<4;j++){ acc[i][j][0]=0.f; acc[i][j][1]=0.f; acc[i][j][2]=0.f; acc[i][j][3]=0.f; }

    const int nkb = K >> 6;
    {
        uint32_t ao = asBase + sOff, bo = bsBase + sOff;
        #pragma unroll
        for (int i=0;i<4;i++){
            CPA(ao + i*32*SPITCH*2, aSrc + (size_t)i*32*K);
            CPA(bo + i*32*SPITCH*2, bSrc + (size_t)i*32*K);
        }
        CPC();
    }

    for (int kb=0; kb<nkb; kb++){
        const int st = kb & 1;
        if (kb+1 < nkb){
            uint32_t ao = asBase + (st^1)*STAGEB + sOff;
            uint32_t bo = bsBase + (st^1)*STAGEB + sOff;
            const __half* ap = aSrc + (size_t)(kb+1)*64;
            const __half* bp = bSrc + (size_t)(kb+1)*64;
            #pragma unroll
            for (int i=0;i<4;i++){
                CPA(ao + i*32*SPITCH*2, ap + (size_t)i*32*K);
                CPA(bo + i*32*SPITCH*2, bp + (size_t)i*32*K);
            }
            CPC();
            CPW(1);
        } else {
            CPW(0);
        }
        __syncthreads();

        const uint32_t aW = asBase + st*STAGEB;
        const uint32_t bW = bsBase + st*STAGEB;
        #pragma unroll
        for (int kc=0;kc<4;kc++){
            uint32_t af[4][4], bf[2][4];
            #pragma unroll
            for (int mi=0;mi<4;mi++){
                int r = wm + mi*16 + (lane&15);
                int c = kc*16 + (lane>>4)*8;
                LDSM4(af[mi][0],af[mi][1],af[mi][2],af[mi][3], aW + (uint32_t)(r*SPITCH + c)*2);
            }
            #pragma unroll
            for (int nj=0;nj<2;nj++){
                int r = wn + nj*16 + (lane>>4)*8 + (lane&7);
                int c = kc*16 + ((lane>>3)&1)*8;
                LDSM4(bf[nj][0],bf[nj][1],bf[nj][2],bf[nj][3], bW + (uint32_t)(r*SPITCH + c)*2);
            }
            #pragma unroll
            for (int mi=0;mi<4;mi++){
                #pragma unroll
                for (int nj=0;nj<2;nj++){
                    mma16816(acc[mi][2*nj  ], af[mi], bf[nj][0], bf[nj][1]);
                    mma16816(acc[mi][2*nj+1], af[mi], bf[nj][2], bf[nj][3]);
                }
            }
        }
        __syncthreads();
    }

    #pragma unroll
    for (int mi=0;mi<4;mi++){
        #pragma unroll
        for (int ni=0;ni<4;ni++){
            int r0 = m0 + wm + mi*16 + g;
            int r1 = r0 + 8;
            int c  = n0 + wn + ni*8 + 2*tg;
            size_t o0 = (size_t)r0*N + c;
            size_t o1 = (size_t)r1*N + c;
            float v0=acc[mi][ni][0], v1=acc[mi][ni][1], v2=acc[mi][ni][2], v3=acc[mi][ni][3];
            if (mode == 1){
                v0 += Resf[o0]; v1 += Resf[o0+1]; v2 += Resf[o1]; v3 += Resf[o1+1];
                *(float2*)&Cf[o0] = make_float2(v0,v1);
                *(float2*)&Cf[o1] = make_float2(v2,v3);
            } else if (mode == 2){
                float g0 = __half2float(Resh[o0]), g1 = __half2float(Resh[o0+1]);
                float g2 = __half2float(Resh[o1]), g3 = __half2float(Resh[o1+1]);
                v0 *= g0/(1.f+__expf(-g0)); v1 *= g1/(1.f+__expf(-g1));
                v2 *= g2/(1.f+__expf(-g2)); v3 *= g3/(1.f+__expf(-g3));
                *(__half2*)&Ch[o0] = __floats2half2_rn(v0,v1);
                *(__half2*)&Ch[o1] = __floats2half2_rn(v2,v3);
            } else if (mode == 3){
                *(__half2*)&Ch[o0] = __floats2half2_rn(v0*0.125f, v1*0.125f);
                *(__half2*)&Ch[o1] = __floats2half2_rn(v2*0.125f, v3*0.125f);
            } else {
                *(__half2*)&Ch[o0] = __floats2half2_rn(v0,v1);
                *(__half2*)&Ch[o1] = __floats2half2_rn(v2,v3);
            }
        }
    }
}

// ---------------- flash attention (cp.async + ldmatrix, mma.sync) ----------------
__global__ __launch_bounds__(256,1)
void flash3(const __half* __restrict__ qh, const __half* __restrict__ kh,
            const __half* __restrict__ vh, __half* __restrict__ oh,
            const int* __restrict__ cuq, const int* __restrict__ cuk)
{
    extern __shared__ __half sm[];
    uint32_t ksBase = (uint32_t)__cvta_generic_to_shared(sm);
    uint32_t vsBase = ksBase + 2*STAGEB;

    const int tid  = threadIdx.x;
    const int lane = tid & 31, warp = tid >> 5;
    const int g = lane >> 2, tg = lane & 3;
    const int bh = blockIdx.y;
    const int b = bh >> 5, h = bh & 31, kv = h >> 2;
    const int q0 = blockIdx.x * 128;
    const int wq = warp * 16;

    const int cq1 = cuq[1], cq2 = cuq[2];
    const int ck1 = cuk[1], ck2 = cuk[2];

    const int qg0 = q0 + wq + g, qg1 = qg0 + 8;
    const __half* qr0 = qh + ((size_t)(b*QLEN + qg0))*HIDDEN + h*HD;
    const __half* qr1 = qh + ((size_t)(b*QLEN + qg1))*HIDDEN + h*HD;
    uint32_t qf[4][4];
    #pragma unroll
    for (int kc=0;kc<4;kc++){
        qf[kc][0] = *(const uint32_t*)(qr0 + kc*16 + 2*tg);
        qf[kc][1] = *(const uint32_t*)(qr1 + kc*16 + 2*tg);
        qf[kc][2] = *(const uint32_t*)(qr0 + kc*16 + 2*tg + 8);
        qf[kc][3] = *(const uint32_t*)(qr1 + kc*16 + 2*tg + 8);
    }

    const int sq0 = (qg0>=cq1)+(qg0>=cq2);
    const int sq1 = (qg1>=cq1)+(qg1>=cq2);
    const int wlo = q0 + wq, whi = wlo + 15;
    const int sqa = (wlo>=cq1)+(wlo>=cq2);
    const int sqb = (whi>=cq1)+(whi>=cq2);

    float oacc[8][4];
    #pragma unroll
    for (int i=0;i<8;i++){ oacc[i][0]=0.f; oacc[i][1]=0.f; oacc[i][2]=0.f; oacc[i][3]=0.f; }
    float mr0 = -1e20f, mr1 = -1e20f, l0 = 0.f, l1 = 0.f;

    int segA = (q0>=cq1)+(q0>=cq2);
    int segB = (q0+127>=cq1)+(q0+127>=cq2);
    int klo, khi;
    if (segA == segB){
        int klos = (segA==0) ? 0 : ((segA==1) ? ck1 : ck2);
        int khis = (segA==0) ? ck1 : ((segA==1) ? ck2 : KLEN);
        klo = klos;
        khi = min(khis, q0+128);
    } else { klo = 0; khi = q0+128; }
    const int t0 = klo >> 7, t1 = (khi + 127) >> 7;

    const __half* kBase = kh + (size_t)(b*NKV+kv)*KLEN*HD;
    const __half* vBase = vh + (size_t)(b*NKV+kv)*KLEN*HD;
    const int crow = tid>>3, cchk = tid&7;
    const uint32_t sOff = (uint32_t)(crow*SPITCH*2 + cchk*16);

    {
        uint32_t ko = ksBase + sOff, vo = vsBase + sOff;
        const __half* kp = kBase + (size_t)(t0*128 + crow)*HD + cchk*8;
        const __half* vp = vBase + (size_t)(t0*128 + crow)*HD + cchk*8;
        #pragma unroll
        for (int i=0;i<4;i++){
            CPA(ko + i*32*SPITCH*2, kp + (size_t)i*32*HD);
            CPA(vo + i*32*SPITCH*2, vp + (size_t)i*32*HD);
        }
        CPC();
    }

    for (int t=t0; t<t1; t++){
        const int st = (t - t0) & 1;
        const int k0 = t << 7;
        if (t+1 < t1){
            uint32_t ko = ksBase + (st^1)*STAGEB + sOff;
            uint32_t vo = vsBase + (st^1)*STAGEB + sOff;
            const __half* kp = kBase + (size_t)((t+1)*128 + crow)*HD + cchk*8;
            const __half* vp = vBase + (size_t)((t+1)*128 + crow)*HD + cchk*8;
            #pragma unroll
            for (int i=0;i<4;i++){
                CPA(ko + i*32*SPITCH*2, kp + (size_t)i*32*HD);
                CPA(vo + i*32*SPITCH*2, vp + (size_t)i*32*HD);
            }
            CPC();
            CPW(1);
        } else {
            CPW(0);
        }
        __syncthreads();

        const uint32_t kW = ksBase + st*STAGEB;
        const uint32_t vW = vsBase + st*STAGEB;

        float sacc[16][4];
        #pragma unroll
        for (int ni=0;ni<16;ni++){ sacc[ni][0]=0.f; sacc[ni][1]=0.f; sacc[ni][2]=0.f; sacc[ni][3]=0.f; }
        #pragma unroll
        for (int kc=0;kc<4;kc++){
            #pragma unroll
            for (int nj=0;nj<8;nj++){
                uint32_t b0,b1,b2,b3;
                int r = nj*16 + (lane>>4)*8 + (lane&7);
                int c = kc*16 + ((lane>>3)&1)*8;
                LDSM4(b0,b1,b2,b3, kW + (uint32_t)(r*SPITCH + c)*2);
                mma16816(sacc[2*nj  ], qf[kc], b0, b1);
                mma16816(sacc[2*nj+1], qf[kc], b2, b3);
            }
        }

        int s_k0   = (k0>=ck1)+(k0>=ck2);
        int s_k127 = (k0+127>=ck1)+(k0+127>=ck2);
        bool fullok = (k0+127 <= wlo) && (s_k0==sqa) && (s_k127==sqa) && (sqa==sqb);
        if (!fullok){
            #pragma unroll
            for (int ni=0;ni<16;ni++){
                int kg = k0 + ni*8 + 2*tg;
                int sk0 = (kg>=ck1)+(kg>=ck2);
                int sk1 = (kg+1>=ck1)+(kg+1>=ck2);
                if (!((kg   <= qg0) && (sk0==sq0))) sacc[ni][0] = -1e30f;
                if (!((kg+1 <= qg0) && (sk1==sq0))) sacc[ni][1] = -1e30f;
                if (!((kg   <= qg1) && (sk0==sq1))) sacc[ni][2] = -1e30f;
                if (!((kg+1 <= qg1) && (sk1==sq1))) sacc[ni][3] = -1e30f;
            }
        }

        float tm0 = -1e20f, tm1 = -1e20f;
        #pragma unroll
        for (int ni=0;ni<16;ni++){
            tm0 = fmaxf(tm0, fmaxf(sacc[ni][0], sacc[ni][1]));
            tm1 = fmaxf(tm1, fmaxf(sacc[ni][2], sacc[ni][3]));
        }
        tm0 = fmaxf(tm0, __shfl_xor_sync(0xffffffffu, tm0, 1));
        tm0 = fmaxf(tm0, __shfl_xor_sync(0xffffffffu, tm0, 2));
        tm1 = fmaxf(tm1, __shfl_xor_sync(0xffffffffu, tm1, 1));
        tm1 = fmaxf(tm1, __shfl_xor_sync(0xffffffffu, tm1, 2));
        float mn0 = fmaxf(mr0, tm0), mn1 = fmaxf(mr1, tm1);
        float sc0 = __expf(mr0 - mn0), sc1 = __expf(mr1 - mn1);
        l0 *= sc0; l1 *= sc1;
        #pragma unroll
        for (int nd=0;nd<8;nd++){
            oacc[nd][0]*=sc0; oacc[nd][1]*=sc0; oacc[nd][2]*=sc1; oacc[nd][3]*=sc1;
        }
        uint32_t pf[8][4];
        float rs0 = 0.f, rs1 = 0.f;
        #pragma unroll
        for (int j=0;j<8;j++){
            float p00 = __expf(sacc[2*j][0]-mn0),   p01 = __expf(sacc[2*j][1]-mn0);
            float p10 = __expf(sacc[2*j][2]-mn1),   p11 = __expf(sacc[2*j][3]-mn1);
            float q00 = __expf(sacc[2*j+1][0]-mn0), q01 = __expf(sacc[2*j+1][1]-mn0);
            float q10 = __expf(sacc[2*j+1][2]-mn1), q11 = __expf(sacc[2*j+1][3]-mn1);
            rs0 += p00+p01+q00+q01;
            rs1 += p10+p11+q10+q11;
            pf[j][0] = packh2(p00,p01);
            pf[j][1] = packh2(p10,p11);
            pf[j][2] = packh2(q00,q01);
            pf[j][3] = packh2(q10,q11);
        }
        rs0 += __shfl_xor_sync(0xffffffffu, rs0, 1);
        rs0 += __shfl_xor_sync(0xffffffffu, rs0, 2);
        rs1 += __shfl_xor_sync(0xffffffffu, rs1, 1);
        rs1 += __shfl_xor_sync(0xffffffffu, rs1, 2);
        l0 += rs0; l1 += rs1;
        mr0 = mn0; mr1 = mn1;

        #pragma unroll
        for (int j=0;j<8;j++){
            #pragma unroll
            for (int dq=0;dq<4;dq++){
                uint32_t b0,b1,b2,b3;
                int r = j*16 + ((lane>>3)&1)*8 + (lane&7);
                int c = dq*16 + (lane>>4)*8;
                LDSM4T(b0,b1,b2,b3, vW + (uint32_t)(r*SPITCH + c)*2);
                mma16816(oacc[2*dq  ], pf[j], b0, b1);
                mma16816(oacc[2*dq+1], pf[j], b2, b3);
            }
        }
        __syncthreads();
    }

    float inv0 = (l0 > 0.f) ? 1.f/l0 : 0.f;
    float inv1 = (l1 > 0.f) ? 1.f/l1 : 0.f;
    __half* or0 = oh + ((size_t)(b*QLEN + qg0))*HIDDEN + h*HD;
    __half* or1 = oh + ((size_t)(b*QLEN + qg1))*HIDDEN + h*HD;
    #pragma unroll
    for (int nd=0;nd<8;nd++){
        int c = nd*8 + 2*tg;
        *(__half2*)&or0[c] = __floats2half2_rn(oacc[nd][0]*inv0, oacc[nd][1]*inv0);
        *(__half2*)&or1[c] = __floats2half2_rn(oacc[nd][2]*inv1, oacc[nd][3]*inv1);
    }
}

// ---------------- launch ----------------
extern "C" void kernel_launch(void* const* d_in, const int* in_sizes, int n_in,
                              void* d_out, int out_size)
{
    const float* hs   = (const float*)d_in[0];
    const float* kst  = (const float*)d_in[1];
    const float* vst  = (const float*)d_in[2];
    const float* wln1 = (const float*)d_in[4];
    const float* wln2 = (const float*)d_in[5];
    const float* wq   = (const float*)d_in[6];
    const float* wo   = (const float*)d_in[7];
    const float* wg   = (const float*)d_in[8];
    const float* wu   = (const float*)d_in[9];
    const float* wd   = (const float*)d_in[10];
    const int*   cuq  = (const int*)d_in[11];
    const int*   cuk  = (const int*)d_in[12];
    float* out = (float*)d_out;

    __half *wqh,*woh,*wgh,*wuh,*wdh,*kh,*vh,*n1h,*qh,*ath,*n2h,*gth,*ach;
    float *hid;
    cudaGetSymbolAddress((void**)&wqh, g_wqh);
    cudaGetSymbolAddress((void**)&woh, g_woh);
    cudaGetSymbolAddress((void**)&wgh, g_wgh);
    cudaGetSymbolAddress((void**)&wuh, g_wuh);
    cudaGetSymbolAddress((void**)&wdh, g_wdh);
    cudaGetSymbolAddress((void**)&kh,  g_kh);
    cudaGetSymbolAddress((void**)&vh,  g_vh);
    cudaGetSymbolAddress((void**)&n1h, g_n1h);
    cudaGetSymbolAddress((void**)&qh,  g_qh);
    cudaGetSymbolAddress((void**)&ath, g_ath);
    cudaGetSymbolAddress((void**)&n2h, g_n2h);
    cudaGetSymbolAddress((void**)&gth, g_gth);
    cudaGetSymbolAddress((void**)&ach, g_ach);
    cudaGetSymbolAddress((void**)&hid, g_hid);

    // runtime dispatch: did the loaded SASS pass get the real tcgen05 body?
    cudaFuncAttributes fa; fa.numRegs = 0;
    cudaFuncGetAttributes(&fa, (const void*)gemm_tc);
    const bool use_tc = (fa.numRegs > 32);

    const int FSMEM = 4*STAGEB;
    cudaFuncSetAttribute(flash3, cudaFuncAttributeMaxDynamicSharedMemorySize, FSMEM);
    if (use_tc){
        cudaFuncSetAttribute(gemm_tc, cudaFuncAttributeMaxDynamicSharedMemorySize, TC_SMEM);
    } else {
        cudaFuncSetAttribute(gemm16, cudaFuncAttributeMaxDynamicSharedMemorySize, FSMEM);
    }

    const int HH = HIDDEN*HIDDEN, IH = INTER*HIDDEN;
    f2h4<<<(HH/4+255)/256, 256>>>(wq, wqh, HH);
    f2h4<<<(HH/4+255)/256, 256>>>(wo, woh, HH);
    f2h4<<<(IH/4+255)/256, 256>>>(wg, wgh, IH);
    f2h4<<<(IH/4+255)/256, 256>>>(wu, wuh, IH);
    f2h4<<<(IH/4+255)/256, 256>>>(wd, wdh, IH);
    convkv<<<(BATCH*KLEN*NKV*(HD/2)+255)/256, 256>>>(kst, vst, kh, vh);

    rmsnorm_h<<<MTOT, 256>>>(hs, wln1, n1h);

    if (use_tc){
        gemm_tc<<<dim3(HIDDEN/256, MTOT/256), 256, TC_SMEM>>>(n1h, wqh, nullptr, qh, nullptr, nullptr, MTOT, HIDDEN, HIDDEN, 3);
        flash3<<<dim3(QLEN/128, BATCH*NHEADS), 256, FSMEM>>>(qh, kh, vh, ath, cuq, cuk);
        gemm_tc<<<dim3(HIDDEN/256, MTOT/256), 256, TC_SMEM>>>(ath, woh, hid, nullptr, nullptr, hs, MTOT, HIDDEN, HIDDEN, 1);
        rmsnorm_h<<<MTOT, 256>>>(hid, wln2, n2h);
        gemm_tc<<<dim3(INTER/256, MTOT/256), 256, TC_SMEM>>>(n2h, wgh, nullptr, gth, nullptr, nullptr, MTOT, INTER, HIDDEN, 0);
        gemm_tc<<<dim3(INTER/256, MTOT/256), 256, TC_SMEM>>>(n2h, wuh, nullptr, ach, gth, nullptr, MTOT, INTER, HIDDEN, 2);
        gemm_tc<<<dim3(HIDDEN/256, MTOT/256), 256, TC_SMEM>>>(ach, wdh, out, nullptr, nullptr, hid, MTOT, HIDDEN, INTER, 1);
    } else {
        gemm16<<<dim3(HIDDEN/128, MTOT/128), 256, FSMEM>>>(n1h, wqh, nullptr, qh, nullptr, nullptr, MTOT, HIDDEN, HIDDEN, 3);
        flash3<<<dim3(QLEN/128, BATCH*NHEADS), 256, FSMEM>>>(qh, kh, vh, ath, cuq, cuk);
        gemm16<<<dim3(HIDDEN/128, MTOT/128), 256, FSMEM>>>(ath, woh, hid, nullptr, nullptr, hs, MTOT, HIDDEN, HIDDEN, 1);
        rmsnorm_h<<<MTOT, 256>>>(hid, wln2, n2h);
        gemm16<<<dim3(INTER/128, MTOT/128), 256, FSMEM>>>(n2h, wgh, nullptr, gth, nullptr, nullptr, MTOT, INTER, HIDDEN, 0);
        gemm16<<<dim3(INTER/128, MTOT/128), 256, FSMEM>>>(n2h, wuh, nullptr, ach, gth, nullptr, MTOT, INTER, HIDDEN, 2);
        gemm16<<<dim3(HIDDEN/128, MTOT/128), 256, FSMEM>>>(ach, wdh, out, nullptr, nullptr, hid, MTOT, HIDDEN, INTER, 1);
    }
}

// round 6
// speedup vs baseline: 8.0944x; 1.0238x over previous
#include <cuda_runtime.h>
#include <cuda_fp16.h>
#include <cstdint>
#include <math.h>

#define HIDDEN 2048
#define NHEADS 32
#define NKV    8
#define HD     64
#define INTER  8192
#define BATCH  2
#define QLEN   2048
#define KLEN   2048
#define MTOT   (BATCH*QLEN)

#if defined(__CUDA_ARCH_FEAT_SM103_ALL) || defined(__CUDA_ARCH_FEAT_SM100_ALL)
#define HAS_TCGEN05 1
#else
#define HAS_TCGEN05 0
#endif

// ---------------- scratch ----------------
__device__ __half g_wqh[(size_t)HIDDEN*HIDDEN];
__device__ __half g_woh[(size_t)HIDDEN*HIDDEN];
__device__ __half g_wgh[(size_t)INTER*HIDDEN];
__device__ __half g_wuh[(size_t)INTER*HIDDEN];
__device__ __half g_wdh[(size_t)HIDDEN*INTER];
__device__ __half g_kh [(size_t)BATCH*NKV*KLEN*HD];
__device__ __half g_vh [(size_t)BATCH*NKV*KLEN*HD];
__device__ __half g_n1h[(size_t)MTOT*HIDDEN];
__device__ __half g_qh [(size_t)MTOT*HIDDEN];
__device__ __half g_ath[(size_t)MTOT*HIDDEN];
__device__ __half g_n2h[(size_t)MTOT*HIDDEN];
__device__ __half g_gth[(size_t)MTOT*INTER];
__device__ __half g_ach[(size_t)MTOT*INTER];
__device__ float  g_hid[(size_t)MTOT*HIDDEN];

// ---------------- asm helpers ----------------
#define CPA(dst, src) asm volatile("cp.async.cg.shared.global [%0], [%1], 16;\n" :: "r"(dst), "l"(src))
#define CPC() asm volatile("cp.async.commit_group;\n")
#define CPW(N) asm volatile("cp.async.wait_group %0;\n" :: "n"(N))
#define LDSM4(r0,r1,r2,r3,addr) asm volatile("ldmatrix.sync.aligned.m8n8.x4.shared.b16 {%0,%1,%2,%3}, [%4];\n" \
    : "=r"(r0),"=r"(r1),"=r"(r2),"=r"(r3) : "r"(addr))
#define LDSM4T(r0,r1,r2,r3,addr) asm volatile("ldmatrix.sync.aligned.m8n8.x4.trans.shared.b16 {%0,%1,%2,%3}, [%4];\n" \
    : "=r"(r0),"=r"(r1),"=r"(r2),"=r"(r3) : "r"(addr))

__device__ __forceinline__ uint32_t swz128(uint32_t x){ return x ^ ((x>>3)&0x70); }

__device__ __forceinline__ uint32_t packh2(float a, float b){
    __half2 h = __floats2half2_rn(a, b);
    return *reinterpret_cast<uint32_t*>(&h);
}
__device__ __forceinline__ void mma16816(float* c, const uint32_t* a, uint32_t b0, uint32_t b1){
    asm volatile("mma.sync.aligned.m16n8k16.row.col.f32.f16.f16.f32 "
        "{%0,%1,%2,%3}, {%4,%5,%6,%7}, {%8,%9}, {%0,%1,%2,%3};"
        : "+f"(c[0]), "+f"(c[1]), "+f"(c[2]), "+f"(c[3])
        : "r"(a[0]), "r"(a[1]), "r"(a[2]), "r"(a[3]), "r"(b0), "r"(b1));
}
__device__ __forceinline__ float blockSum(float v){
    __shared__ float sh[8];
    __shared__ float res;
    int lane = threadIdx.x & 31, w = threadIdx.x >> 5;
    #pragma unroll
    for (int o=16;o;o>>=1) v += __shfl_xor_sync(0xffffffffu, v, o);
    if (lane==0) sh[w] = v;
    __syncthreads();
    if (w==0){
        float x = (lane < 8) ? sh[lane] : 0.f;
        #pragma unroll
        for (int o=4;o;o>>=1) x += __shfl_xor_sync(0xffffffffu, x, o);
        if (lane==0) res = x;
    }
    __syncthreads();
    return res;
}

// ---------------- converts ----------------
__global__ void f2h4(const float* __restrict__ s, __half* __restrict__ d, int n){
    int i = (blockIdx.x*256 + threadIdx.x)*4;
    if (i < n){
        float4 v = *(const float4*)(s+i);
        *(__half2*)(d+i)   = __floats2half2_rn(v.x, v.y);
        *(__half2*)(d+i+2) = __floats2half2_rn(v.z, v.w);
    }
}
__global__ void convkv(const float* __restrict__ k, const float* __restrict__ v,
                       __half* __restrict__ kd, __half* __restrict__ vd){
    int idx = blockIdx.x*256 + threadIdx.x;
    if (idx >= BATCH*KLEN*NKV*(HD/2)) return;
    int d2  = idx & 31;
    int kvh = (idx>>5) & 7;
    int kk  = (idx>>8) & 2047;
    int bb  = idx>>19;
    size_t src = (((size_t)(bb*KLEN+kk)*NKV + kvh)*HD) + d2*2;
    size_t dst = (((size_t)(bb*NKV+kvh)*KLEN + kk)*HD) + d2*2;
    float2 kf = *(const float2*)(k+src);
    float2 vf = *(const float2*)(v+src);
    *(__half2*)(kd+dst) = __floats2half2_rn(kf.x, kf.y);
    *(__half2*)(vd+dst) = __floats2half2_rn(vf.x, vf.y);
}

// ---------------- RMSNorm ----------------
__global__ void rmsnorm_h(const float* __restrict__ x, const float* __restrict__ w,
                          __half* __restrict__ o)
{
    size_t row = blockIdx.x;
    const float* xr = x + row*HIDDEN;
    __half* orow = o + row*HIDDEN;
    float s = 0.f;
    for (int i=threadIdx.x; i<HIDDEN; i+=256){ float v = xr[i]; s += v*v; }
    s = blockSum(s);
    float rs = rsqrtf(s*(1.f/HIDDEN) + 1e-5f);
    for (int i=threadIdx.x; i<HIDDEN; i+=256) orow[i] = __float2half(xr[i]*rs*w[i]);
}

// ==================== tcgen05 GEMM (guarded) ====================
#define TCSTAGE 65536
#define TC_SMEM (3*TCSTAGE + 2048)
#define EPITCH 33

#if HAS_TCGEN05
__device__ __forceinline__ uint32_t elect_one_pred(){
    uint32_t pred;
    asm volatile("{\n\t.reg .pred p;\n\telect.sync _|p, 0xFFFFFFFF;\n\tselp.b32 %0, 1, 0, p;\n\t}" : "=r"(pred));
    return pred;
}
#define MBARRIER_INIT(addr, cnt) \
    asm volatile("mbarrier.init.shared.b64 [%0], %1;" :: "r"((uint32_t)(addr)), "r"((uint32_t)(cnt)) : "memory")
__device__ __forceinline__ void mbar_wait(uint32_t mbar, uint32_t phase){
    asm volatile(
        "{\n\t.reg .pred P1;\n\t"
        "WAIT_%=:\n\t"
        "mbarrier.try_wait.parity.acquire.cta.shared::cta.b64 P1, [%0], %1, 0x989680;\n\t"
        "@P1 bra.uni DONE_%=;\n\t"
        "bra.uni WAIT_%=;\n\t"
        "DONE_%=:\n\t}"
        :: "r"(mbar), "r"(phase) : "memory");
}
static __device__ __forceinline__ uint64_t make_desc_sw128(uint32_t addr){
    const uint64_t base =
        (uint64_t(2)  << 61) | (uint64_t(1) << 46) | (uint64_t(64) << 32) | (uint64_t(1) << 16);
    return base | ((uint64_t)(addr >> 4) & 0x3FFF);
}
#define IDESC_F16 ((1u<<4) | (32u<<17) | (8u<<24))
__device__ __forceinline__ void mma_f16_ss(uint32_t d, uint64_t ad, uint64_t bd, uint32_t en){
    asm volatile(
        "{\n\t.reg .pred p;\n\tsetp.ne.u32 p, %5, 0;\n\t"
        "tcgen05.mma.cta_group::1.kind::f16 [%0], %1, %2, %3, {%4,%4,%4,%4}, p;\n\t}"
        :: "r"(d), "l"(ad), "l"(bd), "r"(IDESC_F16), "r"(0u), "r"(en) : "memory");
}
#endif

__global__ __launch_bounds__(256,1)
void gemm_tc(const __half* __restrict__ A, const __half* __restrict__ B,
             float* __restrict__ Cf, __half* __restrict__ Ch,
             const __half* __restrict__ Resh, const float* __restrict__ Resf,
             int M, int N, int K, int mode)
{
#if HAS_TCGEN05
    extern __shared__ char smraw[];
    uint32_t smem0 = (uint32_t)__cvta_generic_to_shared(smraw);
    uint32_t base  = (smem0 + 1023u) & ~1023u;
    char* gbase = smraw + (base - smem0);
    const uint32_t ctrl = base + 3*TCSTAGE;
    const uint32_t mb   = ctrl + 16;

    const int tid = threadIdx.x, lane = tid&31, warp = tid>>5;
    const int m0 = blockIdx.y*256, n0 = blockIdx.x*256;

    if (warp==0)
        asm volatile("tcgen05.alloc.cta_group::1.sync.aligned.shared::cta.b32 [%0], %1;"
            :: "r"(ctrl), "r"(512u) : "memory");
    if (tid==0){
        #pragma unroll
        for (int i=0;i<4;i++) MBARRIER_INIT(mb + i*8, 1);
    }
    __syncthreads();
    uint32_t tmem; asm volatile("ld.shared.b32 %0, [%1];" : "=r"(tmem) : "r"(ctrl));

    const int nkb = K >> 6;
    const int off = tid & 7;
    const int rbase = tid >> 3;

    uint32_t aAddr[3], bAddr[3];
    uint64_t aDesc[3], bDesc[3];
    #pragma unroll
    for (int s=0;s<3;s++){
        aAddr[s] = base + s*TCSTAGE;
        bAddr[s] = base + s*TCSTAGE + 32768;
        aDesc[s] = make_desc_sw128(aAddr[s]);
        bDesc[s] = make_desc_sw128(bAddr[s]);
    }
    uint32_t swOff[8];
    #pragma unroll
    for (int i=0;i<8;i++){
        uint32_t bo = (uint32_t)((rbase + i*32)*128 + off*16);
        swOff[i] = swz128(bo);
    }

    const __half* aTh = A + (size_t)m0*K + off*8;
    const __half* bTh = B + (size_t)n0*K + off*8;

    #pragma unroll
    for (int c=0;c<2;c++){
        const __half* ap = aTh + (size_t)c*64;
        const __half* bp = bTh + (size_t)c*64;
        #pragma unroll
        for (int i=0;i<8;i++){
            size_t ro = (size_t)(rbase + i*32)*K;
            CPA(aAddr[c] + swOff[i], ap + ro);
            CPA(bAddr[c] + swOff[i], bp + ro);
        }
        CPC();
    }

    for (int t=0; t<nkb; t++){
        const int st = t%3;
        if (t+2 < nkb){
            const int ls = (t+2)%3;
            if (t >= 1) mbar_wait(mb + ls*8, (uint32_t)(((t-1)/3)&1));
            const __half* ap = aTh + (size_t)(t+2)*64;
            const __half* bp = bTh + (size_t)(t+2)*64;
            #pragma unroll
            for (int i=0;i<8;i++){
                size_t ro = (size_t)(rbase + i*32)*K;
                CPA(aAddr[ls] + swOff[i], ap + ro);
                CPA(bAddr[ls] + swOff[i], bp + ro);
            }
            CPC();
            CPW(2);
        } else if (t+1 < nkb){
            CPW(1);
        } else {
            CPW(0);
        }
        __syncthreads();
        asm volatile("fence.proxy.async.shared::cta;" ::: "memory");
        if (warp==0){
            asm volatile("tcgen05.fence::after_thread_sync;" ::: "memory");
            if (elect_one_pred()){
                #pragma unroll
                for (int hf=0; hf<2; hf++){
                    #pragma unroll
                    for (int kc=0;kc<4;kc++){
                        mma_f16_ss(tmem + hf*256,
                                   aDesc[st] + hf*1024 + kc*2,
                                   bDesc[st] + kc*2,
                                   (t>0 || kc>0) ? 1u : 0u);
                    }
                }
                asm volatile("tcgen05.commit.cta_group::1.mbarrier::arrive::one.shared::cluster.b64 [%0];"
                    :: "r"(mb + (uint32_t)st*8) : "memory");
            }
        }
    }

    if (warp==0 && elect_one_pred())
        asm volatile("tcgen05.commit.cta_group::1.mbarrier::arrive::one.shared::cluster.b64 [%0];"
            :: "r"(mb + 24u) : "memory");
    mbar_wait(mb + 24, 0u);
    asm volatile("tcgen05.fence::after_thread_sync;" ::: "memory");
    __syncthreads();

    float* sEp = (float*)gbase;
    const int hf  = warp>>2;
    const int wsb = warp&3;
    const int rr = tid>>3, c4 = (tid&7)*4;

    for (int cc=0; cc<8; cc++){
        uint32_t r[32];
        asm volatile(
            "tcgen05.ld.sync.aligned.32x32b.x32.b32 "
            "{%0, %1, %2, %3, %4, %5, %6, %7, "
            " %8, %9, %10, %11, %12, %13, %14, %15, "
            " %16, %17, %18, %19, %20, %21, %22, %23, "
            " %24, %25, %26, %27, %28, %29, %30, %31}, [%32];"
            : "=r"(r[0]),  "=r"(r[1]),  "=r"(r[2]),  "=r"(r[3]),
              "=r"(r[4]),  "=r"(r[5]),  "=r"(r[6]),  "=r"(r[7]),
              "=r"(r[8]),  "=r"(r[9]),  "=r"(r[10]), "=r"(r[11]),
              "=r"(r[12]), "=r"(r[13]), "=r"(r[14]), "=r"(r[15]),
              "=r"(r[16]), "=r"(r[17]), "=r"(r[18]), "=r"(r[19]),
              "=r"(r[20]), "=r"(r[21]), "=r"(r[22]), "=r"(r[23]),
              "=r"(r[24]), "=r"(r[25]), "=r"(r[26]), "=r"(r[27]),
              "=r"(r[28]), "=r"(r[29]), "=r"(r[30]), "=r"(r[31])
            : "r"(tmem + hf*256 + cc*32));
        asm volatile("tcgen05.wait::ld.sync.aligned;" ::: "memory");
        float* sp = sEp + (hf*128 + wsb*32 + lane)*EPITCH;
        #pragma unroll
        for (int j=0;j<32;j++) sp[j] = __uint_as_float(r[j]);
        __syncthreads();
        #pragma unroll
        for (int i=0;i<8;i++){
            int row = i*32 + rr;
            size_t go = (size_t)(m0 + row)*N + (n0 + cc*32 + c4);
            const float* s4 = sEp + row*EPITCH + c4;
            float v0=s4[0], v1=s4[1], v2=s4[2], v3=s4[3];
            if (mode==1){
                float4 rf = *(const float4*)(Resf + go);
                *(float4*)(Cf + go) = make_float4(v0+rf.x, v1+rf.y, v2+rf.z, v3+rf.w);
            } else if (mode==2){
                uint2 rh = *(const uint2*)(Resh + go);
                __half2 h0 = *(__half2*)&rh.x, h1 = *(__half2*)&rh.y;
                float g0 = __half2float(h0.x), g1 = __half2float(h0.y);
                float g2 = __half2float(h1.x), g3 = __half2float(h1.y);
                v0 *= g0/(1.f+__expf(-g0)); v1 *= g1/(1.f+__expf(-g1));
                v2 *= g2/(1.f+__expf(-g2)); v3 *= g3/(1.f+__expf(-g3));
                *(uint2*)(Ch + go) = make_uint2(packh2(v0,v1), packh2(v2,v3));
            } else if (mode==3){
                *(uint2*)(Ch + go) = make_uint2(packh2(v0*0.125f, v1*0.125f),
                                                packh2(v2*0.125f, v3*0.125f));
            } else {
                *(uint2*)(Ch + go) = make_uint2(packh2(v0,v1), packh2(v2,v3));
            }
        }
        __syncthreads();
    }

    asm volatile("tcgen05.fence::before_thread_sync;" ::: "memory");
    __syncthreads();
    if (warp==0)
        asm volatile("tcgen05.dealloc.cta_group::1.sync.aligned.b32 %0, %1;" :: "r"(tmem), "r"(512u));
#endif
}

// ---------------- fallback fp16 mma.sync GEMM ----------------
#define SPITCH 72
#define STAGEB (128*SPITCH*2)

__global__ __launch_bounds__(256,2)
void gemm16(const __half* __restrict__ A, const __half* __restrict__ B,
            float* __restrict__ Cf, __half* __restrict__ Ch,
            const __half* __restrict__ Resh, const float* __restrict__ Resf,
            int M, int N, int K, int mode)
{
    extern __shared__ __half smf[];
    uint32_t asBase = (uint32_t)__cvta_generic_to_shared(smf);
    uint32_t bsBase = asBase + 2*STAGEB;

    const int tid = threadIdx.x, lane = tid&31, warp = tid>>5;
    const int g = lane>>2, tg = lane&3;
    const int wm = (warp&1)*64, wn = (warp>>1)*32;
    const int m0 = blockIdx.y*128, n0 = blockIdx.x*128;

    const int crow = tid>>3;
    const int cchk = tid&7;
    const uint32_t sOff = (uint32_t)(crow*SPITCH*2 + cchk*16);
    const __half* aSrc = A + (size_t)(m0+crow)*K + cchk*8;
    const __half* bSrc = B + (size_t)(n0+crow)*K + cchk*8;

    float acc[4][4][4];
    #pragma unroll
    for (int i=0;i<4;i++)
        #pragma unroll
        for (int j=0;j<4;j++){ acc[i][j][0]=0.f; acc[i][j][1]=0.f; acc[i][j][2]=0.f; acc[i][j][3]=0.f; }

    const int nkb = K >> 6;
    {
        uint32_t ao = asBase + sOff, bo = bsBase + sOff;
        #pragma unroll
        for (int i=0;i<4;i++){
            CPA(ao + i*32*SPITCH*2, aSrc + (size_t)i*32*K);
            CPA(bo + i*32*SPITCH*2, bSrc + (size_t)i*32*K);
        }
        CPC();
    }

    for (int kb=0; kb<nkb; kb++){
        const int st = kb & 1;
        if (kb+1 < nkb){
            uint32_t ao = asBase + (st^1)*STAGEB + sOff;
            uint32_t bo = bsBase + (st^1)*STAGEB + sOff;
            const __half* ap = aSrc + (size_t)(kb+1)*64;
            const __half* bp = bSrc + (size_t)(kb+1)*64;
            #pragma unroll
            for (int i=0;i<4;i++){
                CPA(ao + i*32*SPITCH*2, ap + (size_t)i*32*K);
                CPA(bo + i*32*SPITCH*2, bp + (size_t)i*32*K);
            }
            CPC();
            CPW(1);
        } else {
            CPW(0);
        }
        __syncthreads();

        const uint32_t aW = asBase + st*STAGEB;
        const uint32_t bW = bsBase + st*STAGEB;
        #pragma unroll
        for (int kc=0;kc<4;kc++){
            uint32_t af[4][4], bf[2][4];
            #pragma unroll
            for (int mi=0;mi<4;mi++){
                int r = wm + mi*16 + (lane&15);
                int c = kc*16 + (lane>>4)*8;
                LDSM4(af[mi][0],af[mi][1],af[mi][2],af[mi][3], aW + (uint32_t)(r*SPITCH + c)*2);
            }
            #pragma unroll
            for (int nj=0;nj<2;nj++){
                int r = wn + nj*16 + (lane>>4)*8 + (lane&7);
                int c = kc*16 + ((lane>>3)&1)*8;
                LDSM4(bf[nj][0],bf[nj][1],bf[nj][2],bf[nj][3], bW + (uint32_t)(r*SPITCH + c)*2);
            }
            #pragma unroll
            for (int mi=0;mi<4;mi++){
                #pragma unroll
                for (int nj=0;nj<2;nj++){
                    mma16816(acc[mi][2*nj  ], af[mi], bf[nj][0], bf[nj][1]);
                    mma16816(acc[mi][2*nj+1], af[mi], bf[nj][2], bf[nj][3]);
                }
            }
        }
        __syncthreads();
    }

    #pragma unroll
    for (int mi=0;mi<4;mi++){
        #pragma unroll
        for (int ni=0;ni<4;ni++){
            int r0 = m0 + wm + mi*16 + g;
            int r1 = r0 + 8;
            int c  = n0 + wn + ni*8 + 2*tg;
            size_t o0 = (size_t)r0*N + c;
            size_t o1 = (size_t)r1*N + c;
            float v0=acc[mi][ni][0], v1=acc[mi][ni][1], v2=acc[mi][ni][2], v3=acc[mi][ni][3];
            if (mode == 1){
                v0 += Resf[o0]; v1 += Resf[o0+1]; v2 += Resf[o1]; v3 += Resf[o1+1];
                *(float2*)&Cf[o0] = make_float2(v0,v1);
                *(float2*)&Cf[o1] = make_float2(v2,v3);
            } else if (mode == 2){
                float g0 = __half2float(Resh[o0]), g1 = __half2float(Resh[o0+1]);
                float g2 = __half2float(Resh[o1]), g3 = __half2float(Resh[o1+1]);
                v0 *= g0/(1.f+__expf(-g0)); v1 *= g1/(1.f+__expf(-g1));
                v2 *= g2/(1.f+__expf(-g2)); v3 *= g3/(1.f+__expf(-g3));
                *(__half2*)&Ch[o0] = __floats2half2_rn(v0,v1);
                *(__half2*)&Ch[o1] = __floats2half2_rn(v2,v3);
            } else if (mode == 3){
                *(__half2*)&Ch[o0] = __floats2half2_rn(v0*0.125f, v1*0.125f);
                *(__half2*)&Ch[o1] = __floats2half2_rn(v2*0.125f, v3*0.125f);
            } else {
                *(__half2*)&Ch[o0] = __floats2half2_rn(v0,v1);
                *(__half2*)&Ch[o1] = __floats2half2_rn(v2,v3);
            }
        }
    }
}

// ---------------- flash attention v4: swizzled 16KB stages, occupancy 2 ----------------
#define FSTG 16384            // 128 rows x 128B, SW128 swizzled
#define FSMEM (4*FSTG)        // K0,K1,V0,V1

__global__ __launch_bounds__(256,2)
void flash4(const __half* __restrict__ qh, const __half* __restrict__ kh,
            const __half* __restrict__ vh, __half* __restrict__ oh,
            const int* __restrict__ cuq, const int* __restrict__ cuk)
{
    extern __shared__ __half sm[];
    uint32_t ksBase = (uint32_t)__cvta_generic_to_shared(sm);
    uint32_t vsBase = ksBase + 2*FSTG;

    const int tid  = threadIdx.x;
    const int lane = tid & 31, warp = tid >> 5;
    const int g = lane >> 2, tg = lane & 3;
    const int bh = blockIdx.y;
    const int b = bh >> 5, h = bh & 31, kv = h >> 2;
    const int q0 = blockIdx.x * 128;
    const int wq = warp * 16;

    const int cq1 = cuq[1], cq2 = cuq[2];
    const int ck1 = cuk[1], ck2 = cuk[2];

    const int qg0 = q0 + wq + g, qg1 = qg0 + 8;
    const __half* qr0 = qh + ((size_t)(b*QLEN + qg0))*HIDDEN + h*HD;
    const __half* qr1 = qh + ((size_t)(b*QLEN + qg1))*HIDDEN + h*HD;
    uint32_t qf[4][4];
    #pragma unroll
    for (int kc=0;kc<4;kc++){
        qf[kc][0] = *(const uint32_t*)(qr0 + kc*16 + 2*tg);
        qf[kc][1] = *(const uint32_t*)(qr1 + kc*16 + 2*tg);
        qf[kc][2] = *(const uint32_t*)(qr0 + kc*16 + 2*tg + 8);
        qf[kc][3] = *(const uint32_t*)(qr1 + kc*16 + 2*tg + 8);
    }

    const int sq0 = (qg0>=cq1)+(qg0>=cq2);
    const int sq1 = (qg1>=cq1)+(qg1>=cq2);
    const int wlo = q0 + wq, whi = wlo + 15;
    const int sqa = (wlo>=cq1)+(wlo>=cq2);
    const int sqb = (whi>=cq1)+(whi>=cq2);

    float oacc[8][4];
    #pragma unroll
    for (int i=0;i<8;i++){ oacc[i][0]=0.f; oacc[i][1]=0.f; oacc[i][2]=0.f; oacc[i][3]=0.f; }
    float mr0 = -1e20f, mr1 = -1e20f, l0 = 0.f, l1 = 0.f;

    int segA = (q0>=cq1)+(q0>=cq2);
    int segB = (q0+127>=cq1)+(q0+127>=cq2);
    int klo, khi;
    if (segA == segB){
        int klos = (segA==0) ? 0 : ((segA==1) ? ck1 : ck2);
        int khis = (segA==0) ? ck1 : ((segA==1) ? ck2 : KLEN);
        klo = klos;
        khi = min(khis, q0+128);
    } else { klo = 0; khi = q0+128; }
    const int t0 = klo >> 7, t1 = (khi + 127) >> 7;

    const __half* kBase = kh + (size_t)(b*NKV+kv)*KLEN*HD;
    const __half* vBase = vh + (size_t)(b*NKV+kv)*KLEN*HD;
    const int crow = tid>>3, cchk = tid&7;
    uint32_t stOff[4];
    #pragma unroll
    for (int i=0;i<4;i++) stOff[i] = swz128((uint32_t)((crow + i*32)*128 + cchk*16));

    {
        const __half* kp = kBase + (size_t)(t0*128 + crow)*HD + cchk*8;
        const __half* vp = vBase + (size_t)(t0*128 + crow)*HD + cchk*8;
        #pragma unroll
        for (int i=0;i<4;i++){
            CPA(ksBase + stOff[i], kp + (size_t)i*32*HD);
            CPA(vsBase + stOff[i], vp + (size_t)i*32*HD);
        }
        CPC();
    }

    for (int t=t0; t<t1; t++){
        const int st = (t - t0) & 1;
        const int k0 = t << 7;
        if (t+1 < t1){
            uint32_t ko = ksBase + (st^1)*FSTG;
            uint32_t vo = vsBase + (st^1)*FSTG;
            const __half* kp = kBase + (size_t)((t+1)*128 + crow)*HD + cchk*8;
            const __half* vp = vBase + (size_t)((t+1)*128 + crow)*HD + cchk*8;
            #pragma unroll
            for (int i=0;i<4;i++){
                CPA(ko + stOff[i], kp + (size_t)i*32*HD);
                CPA(vo + stOff[i], vp + (size_t)i*32*HD);
            }
            CPC();
            CPW(1);
        } else {
            CPW(0);
        }
        __syncthreads();

        const uint32_t kW = ksBase + st*FSTG;
        const uint32_t vW = vsBase + st*FSTG;

        float sacc[16][4];
        #pragma unroll
        for (int ni=0;ni<16;ni++){ sacc[ni][0]=0.f; sacc[ni][1]=0.f; sacc[ni][2]=0.f; sacc[ni][3]=0.f; }
        #pragma unroll
        for (int kc=0;kc<4;kc++){
            #pragma unroll
            for (int nj=0;nj<8;nj++){
                uint32_t b0,b1,b2,b3;
                int r = nj*16 + (lane>>4)*8 + (lane&7);
                int cb = kc*32 + ((lane>>3)&1)*16;
                LDSM4(b0,b1,b2,b3, kW + swz128((uint32_t)(r*128 + cb)));
                mma16816(sacc[2*nj  ], qf[kc], b0, b1);
                mma16816(sacc[2*nj+1], qf[kc], b2, b3);
            }
        }

        int s_k0   = (k0>=ck1)+(k0>=ck2);
        int s_k127 = (k0+127>=ck1)+(k0+127>=ck2);
        bool fullok = (k0+127 <= wlo) && (s_k0==sqa) && (s_k127==sqa) && (sqa==sqb);
        if (!fullok){
            #pragma unroll
            for (int ni=0;ni<16;ni++){
                int kg = k0 + ni*8 + 2*tg;
                int sk0 = (kg>=ck1)+(kg>=ck2);
                int sk1 = (kg+1>=ck1)+(kg+1>=ck2);
                if (!((kg   <= qg0) && (sk0==sq0))) sacc[ni][0] = -1e30f;
                if (!((kg+1 <= qg0) && (sk1==sq0))) sacc[ni][1] = -1e30f;
                if (!((kg   <= qg1) && (sk0==sq1))) sacc[ni][2] = -1e30f;
                if (!((kg+1 <= qg1) && (sk1==sq1))) sacc[ni][3] = -1e30f;
            }
        }

        float tm0 = -1e20f, tm1 = -1e20f;
        #pragma unroll
        for (int ni=0;ni<16;ni++){
            tm0 = fmaxf(tm0, fmaxf(sacc[ni][0], sacc[ni][1]));
            tm1 = fmaxf(tm1, fmaxf(sacc[ni][2], sacc[ni][3]));
        }
        tm0 = fmaxf(tm0, __shfl_xor_sync(0xffffffffu, tm0, 1));
        tm0 = fmaxf(tm0, __shfl_xor_sync(0xffffffffu, tm0, 2));
        tm1 = fmaxf(tm1, __shfl_xor_sync(0xffffffffu, tm1, 1));
        tm1 = fmaxf(tm1, __shfl_xor_sync(0xffffffffu, tm1, 2));
        float mn0 = fmaxf(mr0, tm0), mn1 = fmaxf(mr1, tm1);
        float sc0 = __expf(mr0 - mn0), sc1 = __expf(mr1 - mn1);
        l0 *= sc0; l1 *= sc1;
        #pragma unroll
        for (int nd=0;nd<8;nd++){
            oacc[nd][0]*=sc0; oacc[nd][1]*=sc0; oacc[nd][2]*=sc1; oacc[nd][3]*=sc1;
        }
        uint32_t pf[8][4];
        float rs0 = 0.f, rs1 = 0.f;
        #pragma unroll
        for (int j=0;j<8;j++){
            float p00 = __expf(sacc[2*j][0]-mn0),   p01 = __expf(sacc[2*j][1]-mn0);
            float p10 = __expf(sacc[2*j][2]-mn1),   p11 = __expf(sacc[2*j][3]-mn1);
            float q00 = __expf(sacc[2*j+1][0]-mn0), q01 = __expf(sacc[2*j+1][1]-mn0);
            float q10 = __expf(sacc[2*j+1][2]-mn1), q11 = __expf(sacc[2*j+1][3]-mn1);
            rs0 += p00+p01+q00+q01;
            rs1 += p10+p11+q10+q11;
            pf[j][0] = packh2(p00,p01);
            pf[j][1] = packh2(p10,p11);
            pf[j][2] = packh2(q00,q01);
            pf[j][3] = packh2(q10,q11);
        }
        rs0 += __shfl_xor_sync(0xffffffffu, rs0, 1);
        rs0 += __shfl_xor_sync(0xffffffffu, rs0, 2);
        rs1 += __shfl_xor_sync(0xffffffffu, rs1, 1);
        rs1 += __shfl_xor_sync(0xffffffffu, rs1, 2);
        l0 += rs0; l1 += rs1;
        mr0 = mn0; mr1 = mn1;

        #pragma unroll
        for (int j=0;j<8;j++){
            #pragma unroll
            for (int dq=0;dq<4;dq++){
                uint32_t b0,b1,b2,b3;
                int r = j*16 + ((lane>>3)&1)*8 + (lane&7);
                int cb = dq*32 + (lane>>4)*16;
                LDSM4T(b0,b1,b2,b3, vW + swz128((uint32_t)(r*128 + cb)));
                mma16816(oacc[2*dq  ], pf[j], b0, b1);
                mma16816(oacc[2*dq+1], pf[j], b2, b3);
            }
        }
        __syncthreads();
    }

    float inv0 = (l0 > 0.f) ? 1.f/l0 : 0.f;
    float inv1 = (l1 > 0.f) ? 1.f/l1 : 0.f;
    __half* or0 = oh + ((size_t)(b*QLEN + qg0))*HIDDEN + h*HD;
    __half* or1 = oh + ((size_t)(b*QLEN + qg1))*HIDDEN + h*HD;
    #pragma unroll
    for (int nd=0;nd<8;nd++){
        int c = nd*8 + 2*tg;
        *(__half2*)&or0[c] = __floats2half2_rn(oacc[nd][0]*inv0, oacc[nd][1]*inv0);
        *(__half2*)&or1[c] = __floats2half2_rn(oacc[nd][2]*inv1, oacc[nd][3]*inv1);
    }
}

// ---------------- launch ----------------
extern "C" void kernel_launch(void* const* d_in, const int* in_sizes, int n_in,
                              void* d_out, int out_size)
{
    const float* hs   = (const float*)d_in[0];
    const float* kst  = (const float*)d_in[1];
    const float* vst  = (const float*)d_in[2];
    const float* wln1 = (const float*)d_in[4];
    const float* wln2 = (const float*)d_in[5];
    const float* wq   = (const float*)d_in[6];
    const float* wo   = (const float*)d_in[7];
    const float* wg   = (const float*)d_in[8];
    const float* wu   = (const float*)d_in[9];
    const float* wd   = (const float*)d_in[10];
    const int*   cuq  = (const int*)d_in[11];
    const int*   cuk  = (const int*)d_in[12];
    float* out = (float*)d_out;

    __half *wqh,*woh,*wgh,*wuh,*wdh,*kh,*vh,*n1h,*qh,*ath,*n2h,*gth,*ach;
    float *hid;
    cudaGetSymbolAddress((void**)&wqh, g_wqh);
    cudaGetSymbolAddress((void**)&woh, g_woh);
    cudaGetSymbolAddress((void**)&wgh, g_wgh);
    cudaGetSymbolAddress((void**)&wuh, g_wuh);
    cudaGetSymbolAddress((void**)&wdh, g_wdh);
    cudaGetSymbolAddress((void**)&kh,  g_kh);
    cudaGetSymbolAddress((void**)&vh,  g_vh);
    cudaGetSymbolAddress((void**)&n1h, g_n1h);
    cudaGetSymbolAddress((void**)&qh,  g_qh);
    cudaGetSymbolAddress((void**)&ath, g_ath);
    cudaGetSymbolAddress((void**)&n2h, g_n2h);
    cudaGetSymbolAddress((void**)&gth, g_gth);
    cudaGetSymbolAddress((void**)&ach, g_ach);
    cudaGetSymbolAddress((void**)&hid, g_hid);

    cudaFuncAttributes fa; fa.numRegs = 0;
    cudaFuncGetAttributes(&fa, (const void*)gemm_tc);
    const bool use_tc = (fa.numRegs > 32);

    cudaFuncSetAttribute(flash4, cudaFuncAttributeMaxDynamicSharedMemorySize, FSMEM);
    if (use_tc){
        cudaFuncSetAttribute(gemm_tc, cudaFuncAttributeMaxDynamicSharedMemorySize, TC_SMEM);
    } else {
        cudaFuncSetAttribute(gemm16, cudaFuncAttributeMaxDynamicSharedMemorySize, 4*STAGEB);
    }

    const int HH = HIDDEN*HIDDEN, IH = INTER*HIDDEN;

    // fork: big weight converts overlap with Q-path (Q GEMM + flash)
    cudaStream_t sB;
    cudaStreamCreateWithFlags(&sB, cudaStreamNonBlocking);
    cudaEvent_t eF, eJ;
    cudaEventCreateWithFlags(&eF, cudaEventDisableTiming);
    cudaEventCreateWithFlags(&eJ, cudaEventDisableTiming);
    cudaEventRecord(eF, 0);
    cudaStreamWaitEvent(sB, eF, 0);
    f2h4<<<(HH/4+255)/256, 256, 0, sB>>>(wo, woh, HH);
    f2h4<<<(IH/4+255)/256, 256, 0, sB>>>(wg, wgh, IH);
    f2h4<<<(IH/4+255)/256, 256, 0, sB>>>(wu, wuh, IH);
    f2h4<<<(IH/4+255)/256, 256, 0, sB>>>(wd, wdh, IH);
    cudaEventRecord(eJ, sB);

    // main stream: Q path
    convkv<<<(BATCH*KLEN*NKV*(HD/2)+255)/256, 256>>>(kst, vst, kh, vh);
    f2h4<<<(HH/4+255)/256, 256>>>(wq, wqh, HH);
    rmsnorm_h<<<MTOT, 256>>>(hs, wln1, n1h);

    if (use_tc)
        gemm_tc<<<dim3(HIDDEN/256, MTOT/256), 256, TC_SMEM>>>(n1h, wqh, nullptr, qh, nullptr, nullptr, MTOT, HIDDEN, HIDDEN, 3);
    else
        gemm16<<<dim3(HIDDEN/128, MTOT/128), 256, 4*STAGEB>>>(n1h, wqh, nullptr, qh, nullptr, nullptr, MTOT, HIDDEN, HIDDEN, 3);

    flash4<<<dim3(QLEN/128, BATCH*NHEADS), 256, FSMEM>>>(qh, kh, vh, ath, cuq, cuk);

    // join: need woh/wgh/wuh/wdh from here on
    cudaStreamWaitEvent(0, eJ, 0);

    if (use_tc){
        gemm_tc<<<dim3(HIDDEN/256, MTOT/256), 256, TC_SMEM>>>(ath, woh, hid, nullptr, nullptr, hs, MTOT, HIDDEN, HIDDEN, 1);
        rmsnorm_h<<<MTOT, 256>>>(hid, wln2, n2h);
        gemm_tc<<<dim3(INTER/256, MTOT/256), 256, TC_SMEM>>>(n2h, wgh, nullptr, gth, nullptr, nullptr, MTOT, INTER, HIDDEN, 0);
        gemm_tc<<<dim3(INTER/256, MTOT/256), 256, TC_SMEM>>>(n2h, wuh, nullptr, ach, gth, nullptr, MTOT, INTER, HIDDEN, 2);
        gemm_tc<<<dim3(HIDDEN/256, MTOT/256), 256, TC_SMEM>>>(ach, wdh, out, nullptr, nullptr, hid, MTOT, HIDDEN, INTER, 1);
    } else {
        gemm16<<<dim3(HIDDEN/128, MTOT/128), 256, 4*STAGEB>>>(ath, woh, hid, nullptr, nullptr, hs, MTOT, HIDDEN, HIDDEN, 1);
        rmsnorm_h<<<MTOT, 256>>>(hid, wln2, n2h);
        gemm16<<<dim3(INTER/128, MTOT/128), 256, 4*STAGEB>>>(n2h, wgh, nullptr, gth, nullptr, nullptr, MTOT, INTER, HIDDEN, 0);
        gemm16<<<dim3(INTER/128, MTOT/128), 256, 4*STAGEB>>>(n2h, wuh, nullptr, ach, gth, nullptr, MTOT, INTER, HIDDEN, 2);
        gemm16<<<dim3(HIDDEN/128, MTOT/128), 256, 4*STAGEB>>>(ach, wdh, out, nullptr, nullptr, hid, MTOT, HIDDEN, INTER, 1);
    }

    cudaEventDestroy(eF);
    cudaEventDestroy(eJ);
    cudaStreamDestroy(sB);
}